// round 1
// baseline (speedup 1.0000x reference)
#include <cuda_runtime.h>
#include <math.h>

#define B 64
#define T 256
#define F 64
#define H 1024
#define G4H 4096
#define NCTA 128
#define NTHR 256
#define PSTRIDE 66   // padded batch stride in partial buffer (even, conflict-reducing)

typedef unsigned long long ull;

// ---------------- scratch (device globals; no allocation allowed) ----------------
__device__ __align__(256) float g_xg[(size_t)T * G4H * B];   // [T][4096][B]  256 MB
__device__ __align__(256) float g_actA[(size_t)T * H * B];   // [T][H][B]      64 MB
__device__ __align__(256) float g_actB[(size_t)T * H * B];   // [T][H][B]      64 MB
__device__ __align__(256) float g_hT[2][H * B];              // double-buffered h, [k][b]
__device__ unsigned g_bar_count = 0;
__device__ unsigned g_bar_gen = 0;

// ---------------- helpers ----------------
__device__ __forceinline__ ull splat2(float x) {
    ull r;
    asm("mov.b64 %0, {%1, %1};" : "=l"(r) : "f"(x));
    return r;
}
__device__ __forceinline__ void fma2(ull& d, ull a, ull b) {
    asm("fma.rn.f32x2 %0, %1, %2, %0;" : "+l"(d) : "l"(a), "l"(b));
}
__device__ __forceinline__ float sigf(float x) { return 1.f / (1.f + __expf(-x)); }

__device__ __forceinline__ void grid_barrier() {
    __syncthreads();
    if (threadIdx.x == 0) {
        unsigned gen = *(volatile unsigned*)&g_bar_gen;
        __threadfence();
        unsigned arrived = atomicAdd(&g_bar_count, 1u);
        if (arrived == gridDim.x - 1u) {
            atomicExch(&g_bar_count, 0u);
            __threadfence();
            atomicAdd(&g_bar_gen, 1u);
        } else {
            while (*(volatile unsigned*)&g_bar_gen == gen) { }
        }
    }
    __syncthreads();
}

// Load 32 weight rows (cols of this CTA) transposed into SMEM as Ws[k][32].
__device__ void load_weights(const float* __restrict__ w, int K, float* Ws, int cb) {
    for (int j = 0; j < 32; j++) {
        int cg = ((j >> 3) * H) + cb * 8 + (j & 7);
        const float* src = w + (size_t)cg * K;
        for (int k = threadIdx.x; k < K; k += NTHR)
            Ws[(size_t)k * 32 + j] = src[k];
    }
}

// Accumulate 32 cols x 64 batches over k in [k0,k1) using packed f32x2 FMA.
// Lane tile: 8 cols (colg*8..+8) x 8 batches (batg*8..+8) -> acc[col][batchpair].
template <bool USE_CG>
__device__ __forceinline__ void accum_tile(const float* __restrict__ xin,  // [K][B]
                                           const float* __restrict__ Ws,  // [k][32]
                                           int k0, int k1, int colg, int batg,
                                           ull (&acc)[8][4]) {
#pragma unroll 2
    for (int k = k0; k < k1; k++) {
        const ulonglong2* hp = (const ulonglong2*)(xin + (size_t)k * B + batg * 8);
        ulonglong2 hA, hB;
        if (USE_CG) { hA = __ldcg(hp); hB = __ldcg(hp + 1); }
        else        { hA = __ldg(hp);  hB = __ldg(hp + 1); }
        float4 w0 = *(const float4*)(Ws + (size_t)k * 32 + colg * 8);
        float4 w1 = *(const float4*)(Ws + (size_t)k * 32 + colg * 8 + 4);
        float wv[8] = {w0.x, w0.y, w0.z, w0.w, w1.x, w1.y, w1.z, w1.w};
        ull h4[4] = {hA.x, hA.y, hB.x, hB.y};
        ull ws[8];
#pragma unroll
        for (int j = 0; j < 8; j++) ws[j] = splat2(wv[j]);
#pragma unroll
        for (int j = 0; j < 8; j++)
#pragma unroll
            for (int p = 0; p < 4; p++) fma2(acc[j][p], ws[j], h4[p]);
    }
}

// ---------------- kernel 1: transpose X[b][t][f] -> A[t][f][b] ----------------
__global__ void transpose_kernel(const float* __restrict__ X, float* __restrict__ A) {
    int idx = blockIdx.x * blockDim.x + threadIdx.x;  // b fastest
    if (idx >= T * F * B) return;
    int b = idx & (B - 1);
    int f = (idx >> 6) & (F - 1);
    int t = idx >> 12;
    A[idx] = X[((size_t)b * T + t) * F + f];
}

// ---------------- kernel 2: xg[t][c][b] = W_ih[c,:] . x[t,:,b] + b_ih[c] + b_hh[c] ----
extern "C" __global__ void __launch_bounds__(NTHR, 1)
xg_kernel(const float* __restrict__ w_ih, const float* __restrict__ b_ih,
          const float* __restrict__ b_hh, const float* __restrict__ xin,  // [T][K][B]
          int K) {
    extern __shared__ float smem[];
    float* Ws = smem;                          // K*32
    float* part = Ws + (size_t)K * 32;         // 8*32*PSTRIDE
    float* bias = part + 8 * 32 * PSTRIDE;     // 32
    int cb = blockIdx.x, tid = threadIdx.x;

    load_weights(w_ih, K, Ws, cb);
    if (tid < 32) {
        int cg = ((tid >> 3) * H) + cb * 8 + (tid & 7);
        bias[tid] = b_ih[cg] + b_hh[cg];
    }
    __syncthreads();

    int w = tid >> 5, lane = tid & 31;
    int colg = lane >> 3, batg = lane & 7;
    int kpw = K / 8, k0 = w * kpw;
    int colw = tid >> 3, b0w = (tid & 7) * 8;  // reduce/write mapping
    int cgw = ((colw >> 3) * H) + cb * 8 + (colw & 7);

    for (int t = 0; t < T; t++) {
        ull acc[8][4];
#pragma unroll
        for (int j = 0; j < 8; j++)
#pragma unroll
            for (int p = 0; p < 4; p++) acc[j][p] = 0ull;

        const float* xp = xin + (size_t)t * K * B;
        accum_tile<false>(xp, Ws, k0, k0 + kpw, colg, batg, acc);

        float* pw = part + (size_t)w * 32 * PSTRIDE;
#pragma unroll
        for (int j = 0; j < 8; j++) {
            int col = colg * 8 + j;
#pragma unroll
            for (int p = 0; p < 4; p++)
                *(ull*)(pw + (size_t)col * PSTRIDE + batg * 8 + p * 2) = acc[j][p];
        }
        __syncthreads();

        float s[8];
        float bsum = bias[colw];
#pragma unroll
        for (int i = 0; i < 8; i++) s[i] = bsum;
#pragma unroll
        for (int ww = 0; ww < 8; ww++) {
            const float* q = part + ((size_t)ww * 32 + colw) * PSTRIDE + b0w;
#pragma unroll
            for (int i = 0; i < 8; i++) s[i] += q[i];
        }
        float* dst = g_xg + ((size_t)t * G4H + cgw) * B + b0w;
        float4 v0 = make_float4(s[0], s[1], s[2], s[3]);
        float4 v1 = make_float4(s[4], s[5], s[6], s[7]);
        *(float4*)dst = v0;
        *(float4*)(dst + 4) = v1;
        __syncthreads();
    }
}

// ---------------- kernel 3: recurrent scan (persistent, grid-barrier per step) -----
extern "C" __global__ void __launch_bounds__(NTHR, 1)
rec_kernel(const float* __restrict__ w_hh, float* __restrict__ hseq /* [T][H][B] */) {
    extern __shared__ float smem[];
    float* Ws = smem;                         // H*32
    float* part = Ws + (size_t)H * 32;        // 8*32*PSTRIDE
    int cb = blockIdx.x, tid = threadIdx.x;

    load_weights(w_hh, H, Ws, cb);
    // zero h0 for this CTA's units
    for (int i = tid; i < 8 * B; i += NTHR) {
        int u = cb * 8 + (i >> 6);
        g_hT[0][(size_t)u * B + (i & 63)] = 0.f;
    }
    __syncthreads();
    __threadfence();
    grid_barrier();

    int w = tid >> 5, lane = tid & 31;
    int colg = lane >> 3, batg = lane & 7;
    const int kpw = H / 8;
    int k0 = w * kpw;
    int ul = tid >> 5;            // hidden unit (local) this thread updates
    int b0 = (tid & 31) * 2;      // batch pair
    int uglob = cb * 8 + ul;
    float c0 = 0.f, c1 = 0.f;

    for (int t = 0; t < T; t++) {
        const float* hin = g_hT[t & 1];
        float* hout = g_hT[(t & 1) ^ 1];

        ull acc[8][4];
#pragma unroll
        for (int j = 0; j < 8; j++)
#pragma unroll
            for (int p = 0; p < 4; p++) acc[j][p] = 0ull;

        accum_tile<true>(hin, Ws, k0, k0 + kpw, colg, batg, acc);

        float* pw = part + (size_t)w * 32 * PSTRIDE;
#pragma unroll
        for (int j = 0; j < 8; j++) {
            int col = colg * 8 + j;
#pragma unroll
            for (int p = 0; p < 4; p++)
                *(ull*)(pw + (size_t)col * PSTRIDE + batg * 8 + p * 2) = acc[j][p];
        }
        __syncthreads();

        // gates for cells (uglob, b0) and (uglob, b0+1)
        float z0[4], z1[4];
#pragma unroll
        for (int g = 0; g < 4; g++) {
            int col = g * 8 + ul;
            float sx = 0.f, sy = 0.f;
#pragma unroll
            for (int ww = 0; ww < 8; ww++) {
                float2 q = *(const float2*)(part + ((size_t)ww * 32 + col) * PSTRIDE + b0);
                sx += q.x;
                sy += q.y;
            }
            float2 xgv = *(const float2*)(g_xg + ((size_t)t * G4H + g * H + uglob) * B + b0);
            z0[g] = sx + xgv.x;
            z1[g] = sy + xgv.y;
        }
        float i0 = sigf(z0[0]), f0 = sigf(z0[1]), gg0 = tanhf(z0[2]), o0 = sigf(z0[3]);
        float i1 = sigf(z1[0]), f1 = sigf(z1[1]), gg1 = tanhf(z1[2]), o1 = sigf(z1[3]);
        c0 = f0 * c0 + i0 * gg0;
        c1 = f1 * c1 + i1 * gg1;
        float h0 = o0 * tanhf(c0);
        float h1 = o1 * tanhf(c1);

        *(float2*)(hout + (size_t)uglob * B + b0) = make_float2(h0, h1);
        *(float2*)(hseq + ((size_t)t * H + uglob) * B + b0) = make_float2(h0, h1);

        __threadfence();
        grid_barrier();  // entry __syncthreads also protects `part` reuse
    }
}

// ---------------- kernel 4: out[b][t][f] = tanh(W_out[f,:] . h3[t,:,b] + b_out[f]) ----
__global__ void __launch_bounds__(256)
proj_kernel(const float* __restrict__ hseq, const float* __restrict__ w_out,
            const float* __restrict__ b_out, float* __restrict__ out) {
    __shared__ float Sh[64][68];
    __shared__ float Sw[64][68];  // [k][f]
    int t = blockIdx.x, tid = threadIdx.x;
    int fg = tid >> 4, bg = tid & 15;
    float accv[4][4];
#pragma unroll
    for (int i = 0; i < 4; i++)
#pragma unroll
        for (int j = 0; j < 4; j++) accv[i][j] = 0.f;

    for (int kc = 0; kc < H; kc += 64) {
        __syncthreads();
        {   // stage h chunk: Sh[i][b] = hseq[t][kc+i][b]
            int i = tid >> 2, b = (tid & 3) * 16;
            const float4* src = (const float4*)(hseq + ((size_t)t * H + kc + i) * B + b);
#pragma unroll
            for (int m = 0; m < 4; m++) {
                float4 v = src[m];
                Sh[i][b + m * 4 + 0] = v.x; Sh[i][b + m * 4 + 1] = v.y;
                Sh[i][b + m * 4 + 2] = v.z; Sh[i][b + m * 4 + 3] = v.w;
            }
        }
        {   // stage w chunk transposed: Sw[kk][f] = w_out[f][kc+kk]
            int f = tid >> 2, kk = (tid & 3) * 16;
            const float4* src = (const float4*)(w_out + (size_t)f * H + kc + kk);
#pragma unroll
            for (int m = 0; m < 4; m++) {
                float4 v = src[m];
                Sw[kk + m * 4 + 0][f] = v.x; Sw[kk + m * 4 + 1][f] = v.y;
                Sw[kk + m * 4 + 2][f] = v.z; Sw[kk + m * 4 + 3][f] = v.w;
            }
        }
        __syncthreads();
#pragma unroll 4
        for (int k = 0; k < 64; k++) {
            float4 wv = *(const float4*)&Sw[k][fg * 4];
            float4 hv = *(const float4*)&Sh[k][bg * 4];
            float wr[4] = {wv.x, wv.y, wv.z, wv.w};
            float hr[4] = {hv.x, hv.y, hv.z, hv.w};
#pragma unroll
            for (int i = 0; i < 4; i++)
#pragma unroll
                for (int j = 0; j < 4; j++) accv[i][j] += wr[i] * hr[j];
        }
    }
    int fbase = fg * 4, bbase = bg * 4;
#pragma unroll
    for (int j = 0; j < 4; j++) {
        int b = bbase + j;
        float4 r;
        r.x = tanhf(accv[0][j] + b_out[fbase + 0]);
        r.y = tanhf(accv[1][j] + b_out[fbase + 1]);
        r.z = tanhf(accv[2][j] + b_out[fbase + 2]);
        r.w = tanhf(accv[3][j] + b_out[fbase + 3]);
        *(float4*)(out + ((size_t)b * T + t) * F + fbase) = r;
    }
}

// ---------------- launch ----------------
extern "C" void kernel_launch(void* const* d_in, const int* in_sizes, int n_in,
                              void* d_out, int out_size) {
    const float* X = (const float*)d_in[0];
    const float* w_ih[3] = {(const float*)d_in[1], (const float*)d_in[5], (const float*)d_in[9]};
    const float* w_hh[3] = {(const float*)d_in[2], (const float*)d_in[6], (const float*)d_in[10]};
    const float* b_ih[3] = {(const float*)d_in[3], (const float*)d_in[7], (const float*)d_in[11]};
    const float* b_hh[3] = {(const float*)d_in[4], (const float*)d_in[8], (const float*)d_in[12]};
    const float* w_out = (const float*)d_in[13];
    const float* b_out = (const float*)d_in[14];
    float* out = (float*)d_out;

    float *aA = nullptr, *aB = nullptr;
    cudaGetSymbolAddress((void**)&aA, g_actA);
    cudaGetSymbolAddress((void**)&aB, g_actB);

    const size_t smem_rec = ((size_t)H * 32 + 8 * 32 * PSTRIDE) * sizeof(float);
    const size_t smem_xg1 = ((size_t)F * 32 + 8 * 32 * PSTRIDE + 32) * sizeof(float);
    const size_t smem_xgH = ((size_t)H * 32 + 8 * 32 * PSTRIDE + 32) * sizeof(float);

    cudaFuncSetAttribute(xg_kernel, cudaFuncAttributeMaxDynamicSharedMemorySize, (int)smem_xgH);
    cudaFuncSetAttribute(rec_kernel, cudaFuncAttributeMaxDynamicSharedMemorySize, (int)smem_rec);

    // X -> [T][F][B]
    transpose_kernel<<<(T * F * B + 255) / 256, 256>>>(X, aA);

    // layer 1: in aA (K=F), out aB
    xg_kernel<<<NCTA, NTHR, smem_xg1>>>(w_ih[0], b_ih[0], b_hh[0], aA, F);
    rec_kernel<<<NCTA, NTHR, smem_rec>>>(w_hh[0], aB);

    // layer 2: in aB (K=H), out aA
    xg_kernel<<<NCTA, NTHR, smem_xgH>>>(w_ih[1], b_ih[1], b_hh[1], aB, H);
    rec_kernel<<<NCTA, NTHR, smem_rec>>>(w_hh[1], aA);

    // layer 3: in aA (K=H), out aB
    xg_kernel<<<NCTA, NTHR, smem_xgH>>>(w_ih[2], b_ih[2], b_hh[2], aA, H);
    rec_kernel<<<NCTA, NTHR, smem_rec>>>(w_hh[2], aB);

    // projection
    proj_kernel<<<T, 256>>>(aB, w_out, b_out, out);
}

// round 2
// speedup vs baseline: 1.8088x; 1.8088x over previous
#include <cuda_runtime.h>
#include <math.h>

#define B 64
#define T 256
#define F 64
#define H 1024
#define G4H 4096
#define NCTA 128
#define NTHR 256
#define PSTRIDE 66   // padded batch stride in partial buffer

typedef unsigned long long ull;

// ---------------- scratch (device globals; no allocation allowed) ----------------
__device__ __align__(256) float g_xg[(size_t)T * G4H * B];   // [T][4096][B]
__device__ __align__(256) float g_actA[(size_t)T * H * B];   // [T][H][B]
__device__ __align__(256) float g_actB[(size_t)T * H * B];   // [T][H][B]
__device__ unsigned g_bar_count = 0;
__device__ unsigned g_bar_gen = 0;

// ---------------- helpers ----------------
__device__ __forceinline__ ull splat2(float x) {
    ull r;
    asm("mov.b64 %0, {%1, %1};" : "=l"(r) : "f"(x));
    return r;
}
__device__ __forceinline__ void fma2(ull& d, ull a, ull b) {
    asm("fma.rn.f32x2 %0, %1, %2, %0;" : "+l"(d) : "l"(a), "l"(b));
}
__device__ __forceinline__ float sigf(float x) { return 1.f / (1.f + __expf(-x)); }

__device__ __forceinline__ void grid_barrier() {
    __syncthreads();
    if (threadIdx.x == 0) {
        unsigned gen = *(volatile unsigned*)&g_bar_gen;
        __threadfence();
        unsigned arrived = atomicAdd(&g_bar_count, 1u);
        if (arrived == gridDim.x - 1u) {
            atomicExch(&g_bar_count, 0u);
            __threadfence();
            atomicAdd(&g_bar_gen, 1u);
        } else {
            while (*(volatile unsigned*)&g_bar_gen == gen) { }
        }
    }
    __syncthreads();
}

// Load 32 weight rows (cols of this CTA) transposed into SMEM as Ws[k][32].
__device__ void load_weights(const float* __restrict__ w, int K, float* Ws, int cb) {
    for (int j = 0; j < 32; j++) {
        int cg = ((j >> 3) * H) + cb * 8 + (j & 7);
        const float* src = w + (size_t)cg * K;
        for (int k = threadIdx.x; k < K; k += NTHR)
            Ws[(size_t)k * 32 + j] = src[k];
    }
}

template <bool CG>
__device__ __forceinline__ void loadpair(ulonglong2 (&dst)[2], const float* p) {
    const ulonglong2* q = (const ulonglong2*)p;
    if (CG) { dst[0] = __ldcg(q); dst[1] = __ldcg(q + 1); }
    else    { dst[0] = __ldg(q);  dst[1] = __ldg(q + 1); }
}

__device__ __forceinline__ void compute_k(const float* __restrict__ Wp,
                                          const ulonglong2 (&hb)[2], ull (&acc)[8][4]) {
    float4 w0 = *(const float4*)Wp;
    float4 w1 = *(const float4*)(Wp + 4);
    ull h4[4] = {hb[0].x, hb[0].y, hb[1].x, hb[1].y};
    float wv[8] = {w0.x, w0.y, w0.z, w0.w, w1.x, w1.y, w1.z, w1.w};
#pragma unroll
    for (int j = 0; j < 8; j++) {
        ull ws = splat2(wv[j]);
#pragma unroll
        for (int p = 0; p < 4; p++) fma2(acc[j][p], ws, h4[p]);
    }
}

// Accumulate 32 cols x 64 batches over kcnt k's with double-buffered register
// prefetch (4-k chunks) so L2/DRAM latency is hidden under the FMA stream.
// kcnt must be a multiple of 8.
template <bool USE_CG>
__device__ __forceinline__ void accum_tile(const float* __restrict__ xin,  // [K][B]
                                           const float* __restrict__ Ws,  // [k][32]
                                           int k0, int kcnt, int colg, int batg,
                                           ull (&acc)[8][4]) {
    const float* base = xin + (size_t)k0 * B + batg * 8;
    const float* WsK = Ws + (size_t)k0 * 32 + colg * 8;
    ulonglong2 bufA[4][2], bufB[4][2];
#pragma unroll
    for (int i = 0; i < 4; i++) loadpair<USE_CG>(bufA[i], base + (size_t)i * B);

    int nPair = kcnt >> 3;
    for (int c = 0; c < nPair; c++) {
        int kb = c * 8;
        // prefetch kb+4..kb+7 (always in range since kcnt % 8 == 0)
#pragma unroll
        for (int i = 0; i < 4; i++)
            loadpair<USE_CG>(bufB[i], base + (size_t)(kb + 4 + i) * B);
#pragma unroll
        for (int i = 0; i < 4; i++)
            compute_k(WsK + (size_t)(kb + i) * 32, bufA[i], acc);
        // prefetch next chunk kb+8..kb+11 (clamped on last iter; dead loads)
        int kq = (kb + 8 < kcnt) ? kb + 8 : 0;
#pragma unroll
        for (int i = 0; i < 4; i++)
            loadpair<USE_CG>(bufA[i], base + (size_t)(kq + i) * B);
#pragma unroll
        for (int i = 0; i < 4; i++)
            compute_k(WsK + (size_t)(kb + 4 + i) * 32, bufB[i], acc);
    }
}

// ---------------- kernel 1: transpose X[b][t][f] -> A[t][f][b] ----------------
__global__ void transpose_kernel(const float* __restrict__ X, float* __restrict__ A) {
    int idx = blockIdx.x * blockDim.x + threadIdx.x;  // b fastest
    if (idx >= T * F * B) return;
    int b = idx & (B - 1);
    int f = (idx >> 6) & (F - 1);
    int t = idx >> 12;
    A[idx] = X[((size_t)b * T + t) * F + f];
}

// ---------------- kernel 2: xg[t][c][b] = W_ih[c,:] . x[t,:,b] + b_ih[c] + b_hh[c] ----
extern "C" __global__ void __launch_bounds__(NTHR, 1)
xg_kernel(const float* __restrict__ w_ih, const float* __restrict__ b_ih,
          const float* __restrict__ b_hh, const float* __restrict__ xin,  // [T][K][B]
          int K) {
    extern __shared__ float smem[];
    float* Ws = smem;                          // K*32
    float* part = Ws + (size_t)K * 32;         // 8*32*PSTRIDE
    float* bias = part + 8 * 32 * PSTRIDE;     // 32
    int cb = blockIdx.x, tid = threadIdx.x;

    load_weights(w_ih, K, Ws, cb);
    if (tid < 32) {
        int cg = ((tid >> 3) * H) + cb * 8 + (tid & 7);
        bias[tid] = b_ih[cg] + b_hh[cg];
    }
    __syncthreads();

    int w = tid >> 5, lane = tid & 31;
    int colg = lane >> 3, batg = lane & 7;
    int kpw = K / 8, k0 = w * kpw;
    int colw = tid >> 3, b0w = (tid & 7) * 8;  // reduce/write mapping
    int cgw = ((colw >> 3) * H) + cb * 8 + (colw & 7);

    for (int t = 0; t < T; t++) {
        ull acc[8][4];
#pragma unroll
        for (int j = 0; j < 8; j++)
#pragma unroll
            for (int p = 0; p < 4; p++) acc[j][p] = 0ull;

        const float* xp = xin + (size_t)t * K * B;
        accum_tile<false>(xp, Ws, k0, kpw, colg, batg, acc);

        float* pw = part + (size_t)w * 32 * PSTRIDE;
#pragma unroll
        for (int j = 0; j < 8; j++) {
            int col = colg * 8 + j;
#pragma unroll
            for (int p = 0; p < 4; p++)
                *(ull*)(pw + (size_t)col * PSTRIDE + batg * 8 + p * 2) = acc[j][p];
        }
        __syncthreads();

        float s[8];
        float bsum = bias[colw];
#pragma unroll
        for (int i = 0; i < 8; i++) s[i] = bsum;
#pragma unroll
        for (int ww = 0; ww < 8; ww++) {
            const float* q = part + ((size_t)ww * 32 + colw) * PSTRIDE + b0w;
#pragma unroll
            for (int i = 0; i < 8; i++) s[i] += q[i];
        }
        float* dst = g_xg + ((size_t)t * G4H + cgw) * B + b0w;
        *(float4*)dst = make_float4(s[0], s[1], s[2], s[3]);
        *(float4*)(dst + 4) = make_float4(s[4], s[5], s[6], s[7]);
        __syncthreads();
    }
}

// ---------------- kernel 3: recurrent scan (persistent, grid-barrier per step) -----
extern "C" __global__ void __launch_bounds__(NTHR, 1)
rec_kernel(const float* __restrict__ w_hh, float* __restrict__ hseq /* [T][H][B] */) {
    extern __shared__ float smem[];
    float* Ws = smem;                         // H*32
    float* part = Ws + (size_t)H * 32;        // 8*32*PSTRIDE
    int cb = blockIdx.x, tid = threadIdx.x;

    load_weights(w_hh, H, Ws, cb);
    __syncthreads();

    int w = tid >> 5, lane = tid & 31;
    int colg = lane >> 3, batg = lane & 7;
    const int kpw = H / 8;
    int k0 = w * kpw;
    int ul = tid >> 5;            // hidden unit (local) this thread updates
    int b0 = (tid & 31) * 2;      // batch pair
    int uglob = cb * 8 + ul;
    float c0 = 0.f, c1 = 0.f;

    for (int t = 0; t < T; t++) {
        // Prefetch xg gate values early (DRAM latency overlapped with accum)
        float2 xgv[4];
#pragma unroll
        for (int g = 0; g < 4; g++)
            xgv[g] = __ldg((const float2*)(g_xg + ((size_t)t * G4H + g * H + uglob) * B + b0));

        ull acc[8][4];
#pragma unroll
        for (int j = 0; j < 8; j++)
#pragma unroll
            for (int p = 0; p < 4; p++) acc[j][p] = 0ull;

        if (t > 0)   // h_0 = 0: skip matmul at t==0
            accum_tile<true>(hseq + (size_t)(t - 1) * H * B, Ws, k0, kpw, colg, batg, acc);

        float* pw = part + (size_t)w * 32 * PSTRIDE;
#pragma unroll
        for (int j = 0; j < 8; j++) {
            int col = colg * 8 + j;
#pragma unroll
            for (int p = 0; p < 4; p++)
                *(ull*)(pw + (size_t)col * PSTRIDE + batg * 8 + p * 2) = acc[j][p];
        }
        __syncthreads();

        // gates for cells (uglob, b0) and (uglob, b0+1)
        float z0[4], z1[4];
#pragma unroll
        for (int g = 0; g < 4; g++) {
            int col = g * 8 + ul;
            float sx = 0.f, sy = 0.f;
#pragma unroll
            for (int ww = 0; ww < 8; ww++) {
                float2 q = *(const float2*)(part + ((size_t)ww * 32 + col) * PSTRIDE + b0);
                sx += q.x;
                sy += q.y;
            }
            z0[g] = sx + xgv[g].x;
            z1[g] = sy + xgv[g].y;
        }
        float i0 = sigf(z0[0]), f0 = sigf(z0[1]), gg0 = tanhf(z0[2]), o0 = sigf(z0[3]);
        float i1 = sigf(z1[0]), f1 = sigf(z1[1]), gg1 = tanhf(z1[2]), o1 = sigf(z1[3]);
        c0 = f0 * c0 + i0 * gg0;
        c1 = f1 * c1 + i1 * gg1;
        float h0 = o0 * tanhf(c0);
        float h1 = o1 * tanhf(c1);

        *(float2*)(hseq + ((size_t)t * H + uglob) * B + b0) = make_float2(h0, h1);

        __threadfence();
        grid_barrier();  // entry __syncthreads also protects `part` reuse
    }
}

// ---------------- kernel 4: out[b][t][f] = tanh(W_out[f,:] . h3[t,:,b] + b_out[f]) ----
__global__ void __launch_bounds__(256)
proj_kernel(const float* __restrict__ hseq, const float* __restrict__ w_out,
            const float* __restrict__ b_out, float* __restrict__ out) {
    __shared__ float Sh[64][68];
    __shared__ float Sw[64][68];  // [k][f]
    int t = blockIdx.x, tid = threadIdx.x;
    int fg = tid >> 4, bg = tid & 15;
    float accv[4][4];
#pragma unroll
    for (int i = 0; i < 4; i++)
#pragma unroll
        for (int j = 0; j < 4; j++) accv[i][j] = 0.f;

    for (int kc = 0; kc < H; kc += 64) {
        __syncthreads();
        {   // stage h chunk: Sh[i][b] = hseq[t][kc+i][b]
            int i = tid >> 2, b = (tid & 3) * 16;
            const float4* src = (const float4*)(hseq + ((size_t)t * H + kc + i) * B + b);
#pragma unroll
            for (int m = 0; m < 4; m++) {
                float4 v = src[m];
                Sh[i][b + m * 4 + 0] = v.x; Sh[i][b + m * 4 + 1] = v.y;
                Sh[i][b + m * 4 + 2] = v.z; Sh[i][b + m * 4 + 3] = v.w;
            }
        }
        {   // stage w chunk transposed: Sw[kk][f] = w_out[f][kc+kk]
            int f = tid >> 2, kk = (tid & 3) * 16;
            const float4* src = (const float4*)(w_out + (size_t)f * H + kc + kk);
#pragma unroll
            for (int m = 0; m < 4; m++) {
                float4 v = src[m];
                Sw[kk + m * 4 + 0][f] = v.x; Sw[kk + m * 4 + 1][f] = v.y;
                Sw[kk + m * 4 + 2][f] = v.z; Sw[kk + m * 4 + 3][f] = v.w;
            }
        }
        __syncthreads();
#pragma unroll 4
        for (int k = 0; k < 64; k++) {
            float4 wv = *(const float4*)&Sw[k][fg * 4];
            float4 hv = *(const float4*)&Sh[k][bg * 4];
            float wr[4] = {wv.x, wv.y, wv.z, wv.w};
            float hr[4] = {hv.x, hv.y, hv.z, hv.w};
#pragma unroll
            for (int i = 0; i < 4; i++)
#pragma unroll
                for (int j = 0; j < 4; j++) accv[i][j] += wr[i] * hr[j];
        }
    }
    int fbase = fg * 4, bbase = bg * 4;
#pragma unroll
    for (int j = 0; j < 4; j++) {
        int b = bbase + j;
        float4 r;
        r.x = tanhf(accv[0][j] + b_out[fbase + 0]);
        r.y = tanhf(accv[1][j] + b_out[fbase + 1]);
        r.z = tanhf(accv[2][j] + b_out[fbase + 2]);
        r.w = tanhf(accv[3][j] + b_out[fbase + 3]);
        *(float4*)(out + ((size_t)b * T + t) * F + fbase) = r;
    }
}

// ---------------- launch ----------------
extern "C" void kernel_launch(void* const* d_in, const int* in_sizes, int n_in,
                              void* d_out, int out_size) {
    const float* X = (const float*)d_in[0];
    const float* w_ih[3] = {(const float*)d_in[1], (const float*)d_in[5], (const float*)d_in[9]};
    const float* w_hh[3] = {(const float*)d_in[2], (const float*)d_in[6], (const float*)d_in[10]};
    const float* b_ih[3] = {(const float*)d_in[3], (const float*)d_in[7], (const float*)d_in[11]};
    const float* b_hh[3] = {(const float*)d_in[4], (const float*)d_in[8], (const float*)d_in[12]};
    const float* w_out = (const float*)d_in[13];
    const float* b_out = (const float*)d_in[14];
    float* out = (float*)d_out;

    float *aA = nullptr, *aB = nullptr;
    cudaGetSymbolAddress((void**)&aA, g_actA);
    cudaGetSymbolAddress((void**)&aB, g_actB);

    const size_t smem_rec = ((size_t)H * 32 + 8 * 32 * PSTRIDE) * sizeof(float);
    const size_t smem_xg1 = ((size_t)F * 32 + 8 * 32 * PSTRIDE + 32) * sizeof(float);
    const size_t smem_xgH = ((size_t)H * 32 + 8 * 32 * PSTRIDE + 32) * sizeof(float);

    cudaFuncSetAttribute(xg_kernel, cudaFuncAttributeMaxDynamicSharedMemorySize, (int)smem_xgH);
    cudaFuncSetAttribute(rec_kernel, cudaFuncAttributeMaxDynamicSharedMemorySize, (int)smem_rec);

    // X -> [T][F][B]
    transpose_kernel<<<(T * F * B + 255) / 256, 256>>>(X, aA);

    // layer 1: in aA (K=F), out aB
    xg_kernel<<<NCTA, NTHR, smem_xg1>>>(w_ih[0], b_ih[0], b_hh[0], aA, F);
    rec_kernel<<<NCTA, NTHR, smem_rec>>>(w_hh[0], aB);

    // layer 2: in aB (K=H), out aA
    xg_kernel<<<NCTA, NTHR, smem_xgH>>>(w_ih[1], b_ih[1], b_hh[1], aB, H);
    rec_kernel<<<NCTA, NTHR, smem_rec>>>(w_hh[1], aA);

    // layer 3: in aA (K=H), out aB
    xg_kernel<<<NCTA, NTHR, smem_xgH>>>(w_ih[2], b_ih[2], b_hh[2], aA, H);
    rec_kernel<<<NCTA, NTHR, smem_rec>>>(w_hh[2], aB);

    // projection
    proj_kernel<<<T, 256>>>(aB, w_out, b_out, out);
}

// round 3
// speedup vs baseline: 1.8108x; 1.0011x over previous
#include <cuda_runtime.h>
#include <math.h>

#define B 64
#define T 256
#define F 64
#define H 1024
#define G4H 4096
#define NCTA 128
#define NTHR 256
#define PSTRIDE 66   // padded batch stride in partial buffer

typedef unsigned long long ull;

// ---------------- scratch (device globals; no allocation allowed) ----------------
__device__ __align__(256) float g_xg[(size_t)T * G4H * B];   // [T][4096][B]
__device__ __align__(256) float g_actA[(size_t)T * H * B];   // [T][H][B]
__device__ __align__(256) float g_actB[(size_t)T * H * B];   // [T][H][B]
__device__ unsigned g_bar_count = 0;
__device__ unsigned g_bar_gen = 0;

// ---------------- helpers ----------------
__device__ __forceinline__ ull splat2(float x) {
    ull r;
    asm("mov.b64 %0, {%1, %1};" : "=l"(r) : "f"(x));
    return r;
}
__device__ __forceinline__ void fma2(ull& d, ull a, ull b) {
    asm("fma.rn.f32x2 %0, %1, %2, %0;" : "+l"(d) : "l"(a), "l"(b));
}
__device__ __forceinline__ float sigf(float x) { return 1.f / (1.f + __expf(-x)); }

__device__ __forceinline__ void grid_barrier() {
    __syncthreads();
    if (threadIdx.x == 0) {
        unsigned gen = *(volatile unsigned*)&g_bar_gen;
        __threadfence();
        unsigned arrived = atomicAdd(&g_bar_count, 1u);
        if (arrived == gridDim.x - 1u) {
            atomicExch(&g_bar_count, 0u);
            __threadfence();
            atomicAdd(&g_bar_gen, 1u);
        } else {
            while (*(volatile unsigned*)&g_bar_gen == gen) { }
        }
    }
    __syncthreads();
}

// Load 32 weight rows (cols of this CTA) transposed into SMEM as Ws[k][32].
__device__ void load_weights(const float* __restrict__ w, int K, float* Ws, int cb) {
    for (int j = 0; j < 32; j++) {
        int cg = ((j >> 3) * H) + cb * 8 + (j & 7);
        const float* src = w + (size_t)cg * K;
        for (int k = threadIdx.x; k < K; k += NTHR)
            Ws[(size_t)k * 32 + j] = src[k];
    }
}

template <bool CG>
__device__ __forceinline__ void loadpair(ulonglong2 (&dst)[2], const float* p) {
    const ulonglong2* q = (const ulonglong2*)p;
    if (CG) { dst[0] = __ldcg(q); dst[1] = __ldcg(q + 1); }
    else    { dst[0] = __ldg(q);  dst[1] = __ldg(q + 1); }
}

__device__ __forceinline__ void compute_k(const float* __restrict__ Wp,
                                          const ulonglong2 (&hb)[2], ull (&acc)[8][4]) {
    float4 w0 = *(const float4*)Wp;
    float4 w1 = *(const float4*)(Wp + 4);
    ull h4[4] = {hb[0].x, hb[0].y, hb[1].x, hb[1].y};
    float wv[8] = {w0.x, w0.y, w0.z, w0.w, w1.x, w1.y, w1.z, w1.w};
#pragma unroll
    for (int j = 0; j < 8; j++) {
        ull ws = splat2(wv[j]);
#pragma unroll
        for (int p = 0; p < 4; p++) fma2(acc[j][p], ws, h4[p]);
    }
}

// Accumulate 32 cols x 64 batches over kcnt k's with double-buffered register
// prefetch (4-k chunks) so L2/DRAM latency is hidden under the FMA stream.
// kcnt must be a multiple of 8.
template <bool USE_CG>
__device__ __forceinline__ void accum_tile(const float* __restrict__ xin,  // [K][B]
                                           const float* __restrict__ Ws,  // [k][32]
                                           int k0, int kcnt, int colg, int batg,
                                           ull (&acc)[8][4]) {
    const float* base = xin + (size_t)k0 * B + batg * 8;
    const float* WsK = Ws + (size_t)k0 * 32 + colg * 8;
    ulonglong2 bufA[4][2], bufB[4][2];
#pragma unroll
    for (int i = 0; i < 4; i++) loadpair<USE_CG>(bufA[i], base + (size_t)i * B);

    int nPair = kcnt >> 3;
    for (int c = 0; c < nPair; c++) {
        int kb = c * 8;
        // prefetch kb+4..kb+7 (always in range since kcnt % 8 == 0)
#pragma unroll
        for (int i = 0; i < 4; i++)
            loadpair<USE_CG>(bufB[i], base + (size_t)(kb + 4 + i) * B);
#pragma unroll
        for (int i = 0; i < 4; i++)
            compute_k(WsK + (size_t)(kb + i) * 32, bufA[i], acc);
        // prefetch next chunk kb+8..kb+11 (clamped on last iter; dead loads)
        int kq = (kb + 8 < kcnt) ? kb + 8 : 0;
#pragma unroll
        for (int i = 0; i < 4; i++)
            loadpair<USE_CG>(bufA[i], base + (size_t)(kq + i) * B);
#pragma unroll
        for (int i = 0; i < 4; i++)
            compute_k(WsK + (size_t)(kb + 4 + i) * 32, bufB[i], acc);
    }
}

// ---------------- kernel 1: transpose X[b][t][f] -> A[t][f][b] ----------------
__global__ void transpose_kernel(const float* __restrict__ X, float* __restrict__ A) {
    int idx = blockIdx.x * blockDim.x + threadIdx.x;  // b fastest
    if (idx >= T * F * B) return;
    int b = idx & (B - 1);
    int f = (idx >> 6) & (F - 1);
    int t = idx >> 12;
    A[idx] = X[((size_t)b * T + t) * F + f];
}

// ---------------- kernel 2: xg[t][c][b] = W_ih[c,:] . x[t,:,b] + b_ih[c] + b_hh[c] ----
extern "C" __global__ void __launch_bounds__(NTHR, 1)
xg_kernel(const float* __restrict__ w_ih, const float* __restrict__ b_ih,
          const float* __restrict__ b_hh, const float* __restrict__ xin,  // [T][K][B]
          int K) {
    extern __shared__ float smem[];
    float* Ws = smem;                          // K*32
    float* part = Ws + (size_t)K * 32;         // 8*32*PSTRIDE
    float* bias = part + 8 * 32 * PSTRIDE;     // 32
    int cb = blockIdx.x, tid = threadIdx.x;

    load_weights(w_ih, K, Ws, cb);
    if (tid < 32) {
        int cg = ((tid >> 3) * H) + cb * 8 + (tid & 7);
        bias[tid] = b_ih[cg] + b_hh[cg];
    }
    __syncthreads();

    int w = tid >> 5, lane = tid & 31;
    int colg = lane >> 3, batg = lane & 7;
    int kpw = K / 8, k0 = w * kpw;
    int colw = tid >> 3, b0w = (tid & 7) * 8;  // reduce/write mapping
    int cgw = ((colw >> 3) * H) + cb * 8 + (colw & 7);

    for (int t = 0; t < T; t++) {
        ull acc[8][4];
#pragma unroll
        for (int j = 0; j < 8; j++)
#pragma unroll
            for (int p = 0; p < 4; p++) acc[j][p] = 0ull;

        const float* xp = xin + (size_t)t * K * B;
        accum_tile<false>(xp, Ws, k0, kpw, colg, batg, acc);

        float* pw = part + (size_t)w * 32 * PSTRIDE;
#pragma unroll
        for (int j = 0; j < 8; j++) {
            int col = colg * 8 + j;
#pragma unroll
            for (int p = 0; p < 4; p++)
                *(ull*)(pw + (size_t)col * PSTRIDE + batg * 8 + p * 2) = acc[j][p];
        }
        __syncthreads();

        float s[8];
        float bsum = bias[colw];
#pragma unroll
        for (int i = 0; i < 8; i++) s[i] = bsum;
#pragma unroll
        for (int ww = 0; ww < 8; ww++) {
            const float* q = part + ((size_t)ww * 32 + colw) * PSTRIDE + b0w;
#pragma unroll
            for (int i = 0; i < 8; i++) s[i] += q[i];
        }
        float* dst = g_xg + ((size_t)t * G4H + cgw) * B + b0w;
        *(float4*)dst = make_float4(s[0], s[1], s[2], s[3]);
        *(float4*)(dst + 4) = make_float4(s[4], s[5], s[6], s[7]);
        __syncthreads();
    }
}

// ---------------- kernel 3: recurrent scan (persistent, grid-barrier per step) -----
extern "C" __global__ void __launch_bounds__(NTHR, 1)
rec_kernel(const float* __restrict__ w_hh, float* __restrict__ hseq /* [T][H][B] */) {
    extern __shared__ float smem[];
    float* Ws = smem;                         // H*32
    float* part = Ws + (size_t)H * 32;        // 8*32*PSTRIDE
    int cb = blockIdx.x, tid = threadIdx.x;

    load_weights(w_hh, H, Ws, cb);
    __syncthreads();

    int w = tid >> 5, lane = tid & 31;
    int colg = lane >> 3, batg = lane & 7;
    const int kpw = H / 8;
    int k0 = w * kpw;
    int ul = tid >> 5;            // hidden unit (local) this thread updates
    int b0 = (tid & 31) * 2;      // batch pair
    int uglob = cb * 8 + ul;
    float c0 = 0.f, c1 = 0.f;

    for (int t = 0; t < T; t++) {
        // Prefetch xg gate values early (DRAM latency overlapped with accum)
        float2 xgv[4];
#pragma unroll
        for (int g = 0; g < 4; g++)
            xgv[g] = __ldg((const float2*)(g_xg + ((size_t)t * G4H + g * H + uglob) * B + b0));

        ull acc[8][4];
#pragma unroll
        for (int j = 0; j < 8; j++)
#pragma unroll
            for (int p = 0; p < 4; p++) acc[j][p] = 0ull;

        if (t > 0)   // h_0 = 0: skip matmul at t==0
            accum_tile<true>(hseq + (size_t)(t - 1) * H * B, Ws, k0, kpw, colg, batg, acc);

        float* pw = part + (size_t)w * 32 * PSTRIDE;
#pragma unroll
        for (int j = 0; j < 8; j++) {
            int col = colg * 8 + j;
#pragma unroll
            for (int p = 0; p < 4; p++)
                *(ull*)(pw + (size_t)col * PSTRIDE + batg * 8 + p * 2) = acc[j][p];
        }
        __syncthreads();

        // gates for cells (uglob, b0) and (uglob, b0+1)
        float z0[4], z1[4];
#pragma unroll
        for (int g = 0; g < 4; g++) {
            int col = g * 8 + ul;
            float sx = 0.f, sy = 0.f;
#pragma unroll
            for (int ww = 0; ww < 8; ww++) {
                float2 q = *(const float2*)(part + ((size_t)ww * 32 + col) * PSTRIDE + b0);
                sx += q.x;
                sy += q.y;
            }
            z0[g] = sx + xgv[g].x;
            z1[g] = sy + xgv[g].y;
        }
        float i0 = sigf(z0[0]), f0 = sigf(z0[1]), gg0 = tanhf(z0[2]), o0 = sigf(z0[3]);
        float i1 = sigf(z1[0]), f1 = sigf(z1[1]), gg1 = tanhf(z1[2]), o1 = sigf(z1[3]);
        c0 = f0 * c0 + i0 * gg0;
        c1 = f1 * c1 + i1 * gg1;
        float h0 = o0 * tanhf(c0);
        float h1 = o1 * tanhf(c1);

        *(float2*)(hseq + ((size_t)t * H + uglob) * B + b0) = make_float2(h0, h1);

        __threadfence();
        grid_barrier();  // entry __syncthreads also protects `part` reuse
    }
}

// ---------------- kernel 4: out[b][t][f] = tanh(W_out[f,:] . h3[t,:,b] + b_out[f]) ----
__global__ void __launch_bounds__(256)
proj_kernel(const float* __restrict__ hseq, const float* __restrict__ w_out,
            const float* __restrict__ b_out, float* __restrict__ out) {
    __shared__ float Sh[64][68];
    __shared__ float Sw[64][68];  // [k][f]
    int t = blockIdx.x, tid = threadIdx.x;
    int fg = tid >> 4, bg = tid & 15;
    float accv[4][4];
#pragma unroll
    for (int i = 0; i < 4; i++)
#pragma unroll
        for (int j = 0; j < 4; j++) accv[i][j] = 0.f;

    for (int kc = 0; kc < H; kc += 64) {
        __syncthreads();
        {   // stage h chunk: Sh[i][b] = hseq[t][kc+i][b]
            int i = tid >> 2, b = (tid & 3) * 16;
            const float4* src = (const float4*)(hseq + ((size_t)t * H + kc + i) * B + b);
#pragma unroll
            for (int m = 0; m < 4; m++) {
                float4 v = src[m];
                Sh[i][b + m * 4 + 0] = v.x; Sh[i][b + m * 4 + 1] = v.y;
                Sh[i][b + m * 4 + 2] = v.z; Sh[i][b + m * 4 + 3] = v.w;
            }
        }
        {   // stage w chunk transposed: Sw[kk][f] = w_out[f][kc+kk]
            int f = tid >> 2, kk = (tid & 3) * 16;
            const float4* src = (const float4*)(w_out + (size_t)f * H + kc + kk);
#pragma unroll
            for (int m = 0; m < 4; m++) {
                float4 v = src[m];
                Sw[kk + m * 4 + 0][f] = v.x; Sw[kk + m * 4 + 1][f] = v.y;
                Sw[kk + m * 4 + 2][f] = v.z; Sw[kk + m * 4 + 3][f] = v.w;
            }
        }
        __syncthreads();
#pragma unroll 4
        for (int k = 0; k < 64; k++) {
            float4 wv = *(const float4*)&Sw[k][fg * 4];
            float4 hv = *(const float4*)&Sh[k][bg * 4];
            float wr[4] = {wv.x, wv.y, wv.z, wv.w};
            float hr[4] = {hv.x, hv.y, hv.z, hv.w};
#pragma unroll
            for (int i = 0; i < 4; i++)
#pragma unroll
                for (int j = 0; j < 4; j++) accv[i][j] += wr[i] * hr[j];
        }
    }
    int fbase = fg * 4, bbase = bg * 4;
#pragma unroll
    for (int j = 0; j < 4; j++) {
        int b = bbase + j;
        float4 r;
        r.x = tanhf(accv[0][j] + b_out[fbase + 0]);
        r.y = tanhf(accv[1][j] + b_out[fbase + 1]);
        r.z = tanhf(accv[2][j] + b_out[fbase + 2]);
        r.w = tanhf(accv[3][j] + b_out[fbase + 3]);
        *(float4*)(out + ((size_t)b * T + t) * F + fbase) = r;
    }
}

// ---------------- launch ----------------
extern "C" void kernel_launch(void* const* d_in, const int* in_sizes, int n_in,
                              void* d_out, int out_size) {
    const float* X = (const float*)d_in[0];
    const float* w_ih[3] = {(const float*)d_in[1], (const float*)d_in[5], (const float*)d_in[9]};
    const float* w_hh[3] = {(const float*)d_in[2], (const float*)d_in[6], (const float*)d_in[10]};
    const float* b_ih[3] = {(const float*)d_in[3], (const float*)d_in[7], (const float*)d_in[11]};
    const float* b_hh[3] = {(const float*)d_in[4], (const float*)d_in[8], (const float*)d_in[12]};
    const float* w_out = (const float*)d_in[13];
    const float* b_out = (const float*)d_in[14];
    float* out = (float*)d_out;

    float *aA = nullptr, *aB = nullptr;
    cudaGetSymbolAddress((void**)&aA, g_actA);
    cudaGetSymbolAddress((void**)&aB, g_actB);

    const size_t smem_rec = ((size_t)H * 32 + 8 * 32 * PSTRIDE) * sizeof(float);
    const size_t smem_xg1 = ((size_t)F * 32 + 8 * 32 * PSTRIDE + 32) * sizeof(float);
    const size_t smem_xgH = ((size_t)H * 32 + 8 * 32 * PSTRIDE + 32) * sizeof(float);

    cudaFuncSetAttribute(xg_kernel, cudaFuncAttributeMaxDynamicSharedMemorySize, (int)smem_xgH);
    cudaFuncSetAttribute(rec_kernel, cudaFuncAttributeMaxDynamicSharedMemorySize, (int)smem_rec);

    // X -> [T][F][B]
    transpose_kernel<<<(T * F * B + 255) / 256, 256>>>(X, aA);

    // layer 1: in aA (K=F), out aB
    xg_kernel<<<NCTA, NTHR, smem_xg1>>>(w_ih[0], b_ih[0], b_hh[0], aA, F);
    rec_kernel<<<NCTA, NTHR, smem_rec>>>(w_hh[0], aB);

    // layer 2: in aB (K=H), out aA
    xg_kernel<<<NCTA, NTHR, smem_xgH>>>(w_ih[1], b_ih[1], b_hh[1], aB, H);
    rec_kernel<<<NCTA, NTHR, smem_rec>>>(w_hh[1], aA);

    // layer 3: in aA (K=H), out aB
    xg_kernel<<<NCTA, NTHR, smem_xgH>>>(w_ih[2], b_ih[2], b_hh[2], aA, H);
    rec_kernel<<<NCTA, NTHR, smem_rec>>>(w_hh[2], aB);

    // projection
    proj_kernel<<<T, 256>>>(aB, w_out, b_out, out);
}

// round 5
// speedup vs baseline: 2.1296x; 1.1761x over previous
#include <cuda_runtime.h>
#include <cuda_bf16.h>
#include <math.h>

#define B 64
#define T 256
#define F 64
#define H 1024
#define G4H 4096
#define NCTA 128
#define NTHR 256
#define PSTRIDE 66

typedef unsigned long long ull;
typedef unsigned int u32;

// ---------------- scratch globals ----------------
__device__ __align__(256) float g_xg[(size_t)T * G4H * B];   // [T][4096][B]
__device__ __align__(256) float g_actA[(size_t)T * H * B];   // [T][H][B]
__device__ __align__(256) float g_actB[(size_t)T * H * B];   // [T][H][B]
// fragment-packed A image: [parity][kc 0..63][mt 0..7][lane 0..31][16B]
__device__ __align__(256) unsigned char g_hImg[2][64 * 8 * 32 * 16];
__device__ unsigned g_bar_count = 0;
__device__ unsigned g_bar_gen = 0;

// ---------------- generic helpers ----------------
__device__ __forceinline__ ull splat2(float x) {
    ull r; asm("mov.b64 %0, {%1, %1};" : "=l"(r) : "f"(x)); return r;
}
__device__ __forceinline__ void fma2(ull& d, ull a, ull b) {
    asm("fma.rn.f32x2 %0, %1, %2, %0;" : "+l"(d) : "l"(a), "l"(b));
}
__device__ __forceinline__ float sigf(float x) { return 1.f / (1.f + __expf(-x)); }

__device__ __forceinline__ void grid_barrier() {
    __syncthreads();
    if (threadIdx.x == 0) {
        unsigned gen = *(volatile unsigned*)&g_bar_gen;
        __threadfence();
        unsigned arrived = atomicAdd(&g_bar_count, 1u);
        if (arrived == gridDim.x - 1u) {
            atomicExch(&g_bar_count, 0u);
            __threadfence();
            atomicAdd(&g_bar_gen, 1u);
        } else {
            while (*(volatile unsigned*)&g_bar_gen == gen) { }
        }
    }
    __syncthreads();
}

// bf16 pack/split helpers
__device__ __forceinline__ u32 packbf(float a, float b) {
    unsigned short la = __bfloat16_as_ushort(__float2bfloat16_rn(a));
    unsigned short lb = __bfloat16_as_ushort(__float2bfloat16_rn(b));
    return (u32)la | ((u32)lb << 16);
}

// mma.sync m16n8k16 bf16 (base ISA, works on plain sm_103 target)
__device__ __forceinline__ void mma_bf16(float* d, const uint4& a, u32 b0, u32 b1) {
    asm volatile(
        "mma.sync.aligned.m16n8k16.row.col.f32.bf16.bf16.f32 "
        "{%0,%1,%2,%3},{%4,%5,%6,%7},{%8,%9},{%0,%1,%2,%3};"
        : "+f"(d[0]), "+f"(d[1]), "+f"(d[2]), "+f"(d[3])
        : "r"(a.x), "r"(a.y), "r"(a.z), "r"(a.w), "r"(b0), "r"(b1));
}

__device__ __forceinline__ uint4 ldimg(const unsigned char* img, int kc, int mt, int lane) {
    return __ldcg((const uint4*)(img + ((size_t)((kc * 8 + mt) * 32 + lane) << 4)));
}

// ---------------- SIMT GEMM helpers (xg path) ----------------
template <bool CG>
__device__ __forceinline__ void loadpair(ulonglong2 (&dst)[2], const float* p) {
    const ulonglong2* q = (const ulonglong2*)p;
    if (CG) { dst[0] = __ldcg(q); dst[1] = __ldcg(q + 1); }
    else    { dst[0] = __ldg(q);  dst[1] = __ldg(q + 1); }
}
__device__ __forceinline__ void compute_k(const float* __restrict__ Wp,
                                          const ulonglong2 (&hb)[2], ull (&acc)[8][4]) {
    float4 w0 = *(const float4*)Wp;
    float4 w1 = *(const float4*)(Wp + 4);
    ull h4[4] = {hb[0].x, hb[0].y, hb[1].x, hb[1].y};
    float wv[8] = {w0.x, w0.y, w0.z, w0.w, w1.x, w1.y, w1.z, w1.w};
#pragma unroll
    for (int j = 0; j < 8; j++) {
        ull ws = splat2(wv[j]);
#pragma unroll
        for (int p = 0; p < 4; p++) fma2(acc[j][p], ws, h4[p]);
    }
}
template <bool USE_CG>
__device__ __forceinline__ void accum_tile(const float* __restrict__ xin,
                                           const float* __restrict__ Ws,
                                           int k0, int kcnt, int colg, int batg,
                                           ull (&acc)[8][4]) {
    const float* base = xin + (size_t)k0 * B + batg * 8;
    const float* WsK = Ws + (size_t)k0 * 32 + colg * 8;
    ulonglong2 bufA[4][2], bufB[4][2];
#pragma unroll
    for (int i = 0; i < 4; i++) loadpair<USE_CG>(bufA[i], base + (size_t)i * B);
    int nPair = kcnt >> 3;
    for (int c = 0; c < nPair; c++) {
        int kb = c * 8;
#pragma unroll
        for (int i = 0; i < 4; i++)
            loadpair<USE_CG>(bufB[i], base + (size_t)(kb + 4 + i) * B);
#pragma unroll
        for (int i = 0; i < 4; i++)
            compute_k(WsK + (size_t)(kb + i) * 32, bufA[i], acc);
        int kq = (kb + 8 < kcnt) ? kb + 8 : 0;
#pragma unroll
        for (int i = 0; i < 4; i++)
            loadpair<USE_CG>(bufA[i], base + (size_t)(kq + i) * B);
#pragma unroll
        for (int i = 0; i < 4; i++)
            compute_k(WsK + (size_t)(kb + 4 + i) * 32, bufB[i], acc);
    }
}

__device__ void load_weights(const float* __restrict__ w, int K, float* Ws, int cb) {
    for (int j = 0; j < 32; j++) {
        int cg = ((j >> 3) * H) + cb * 8 + (j & 7);
        const float* src = w + (size_t)cg * K;
        for (int k = threadIdx.x; k < K; k += NTHR)
            Ws[(size_t)k * 32 + j] = src[k];
    }
}

// ---------------- kernel 1: transpose X[b][t][f] -> A[t][f][b] ----------------
__global__ void transpose_kernel(const float* __restrict__ X, float* __restrict__ A) {
    int idx = blockIdx.x * blockDim.x + threadIdx.x;
    if (idx >= T * F * B) return;
    int b = idx & (B - 1);
    int f = (idx >> 6) & (F - 1);
    int t = idx >> 12;
    A[idx] = X[((size_t)b * T + t) * F + f];
}

// ---------------- kernel 2: xg (SIMT fp32) ----------------
extern "C" __global__ void __launch_bounds__(NTHR, 1)
xg_kernel(const float* __restrict__ w_ih, const float* __restrict__ b_ih,
          const float* __restrict__ b_hh, const float* __restrict__ xin, int K) {
    extern __shared__ float smemf[];
    float* Ws = smemf;
    float* part = Ws + (size_t)K * 32;
    float* bias = part + 8 * 32 * PSTRIDE;
    int cb = blockIdx.x, tid = threadIdx.x;

    load_weights(w_ih, K, Ws, cb);
    if (tid < 32) {
        int cg = ((tid >> 3) * H) + cb * 8 + (tid & 7);
        bias[tid] = b_ih[cg] + b_hh[cg];
    }
    __syncthreads();

    int w = tid >> 5, lane = tid & 31;
    int colg = lane >> 3, batg = lane & 7;
    int kpw = K / 8, k0 = w * kpw;
    int colw = tid >> 3, b0w = (tid & 7) * 8;
    int cgw = ((colw >> 3) * H) + cb * 8 + (colw & 7);

    for (int t = 0; t < T; t++) {
        ull acc[8][4];
#pragma unroll
        for (int j = 0; j < 8; j++)
#pragma unroll
            for (int p = 0; p < 4; p++) acc[j][p] = 0ull;

        const float* xp = xin + (size_t)t * K * B;
        accum_tile<false>(xp, Ws, k0, kpw, colg, batg, acc);

        float* pw = part + (size_t)w * 32 * PSTRIDE;
#pragma unroll
        for (int j = 0; j < 8; j++) {
            int col = colg * 8 + j;
#pragma unroll
            for (int p = 0; p < 4; p++)
                *(ull*)(pw + (size_t)col * PSTRIDE + batg * 8 + p * 2) = acc[j][p];
        }
        __syncthreads();

        float s[8];
        float bsum = bias[colw];
#pragma unroll
        for (int i = 0; i < 8; i++) s[i] = bsum;
#pragma unroll
        for (int ww = 0; ww < 8; ww++) {
            const float* q = part + ((size_t)ww * 32 + colw) * PSTRIDE + b0w;
#pragma unroll
            for (int i = 0; i < 8; i++) s[i] += q[i];
        }
        float* dst = g_xg + ((size_t)t * G4H + cgw) * B + b0w;
        *(float4*)dst = make_float4(s[0], s[1], s[2], s[3]);
        *(float4*)(dst + 4) = make_float4(s[4], s[5], s[6], s[7]);
        __syncthreads();
    }
}

// ---------------- kernel 3: recurrent scan — HMMA split-bf16 ----------------
// SMEM layout (bytes):
//  Wpack_hi  [64 kc][4 nt][32 lane][2 u32]   65536
//  Wpack_lo  same                            65536
//  Zhi       [128][33] f32                   16896
//  Zlo       [64][33] f32                     8448
//  hsb       [128 R][8 unit] bf16             2048
#define OFF_WHI 0
#define OFF_WLO 65536
#define OFF_ZHI 131072
#define OFF_ZLO 147968
#define OFF_HSB 156416
#define SMEM_REC 158464

extern "C" __global__ void __launch_bounds__(NTHR, 1)
rec_kernel(const float* __restrict__ w_hh, float* __restrict__ hseq) {
    extern __shared__ char smem[];
    const int cb = blockIdx.x, tid = threadIdx.x;
    const int wid = tid >> 5, lane = tid & 31;

    // ---- pack resident W_hh slice into B-fragment layout, split hi/lo ----
    {
        int nt = tid >> 6;            // 0..3
        int l  = (tid >> 1) & 31;
        int word = tid & 1;
        int j = nt * 8 + (l >> 2);    // local col 0..31
        int row = (j >> 3) * H + cb * 8 + (j & 7);
        const float* src = w_hh + (size_t)row * H;
        for (int kc = 0; kc < 64; kc++) {
            int k0 = kc * 16 + (l & 3) * 2 + word * 8;
            float v0 = __ldg(src + k0), v1 = __ldg(src + k0 + 1);
            float h0 = __bfloat162float(__float2bfloat16_rn(v0));
            float h1 = __bfloat162float(__float2bfloat16_rn(v1));
            u32 off = (u32)(((kc * 4 + nt) * 32 + l) * 8 + word * 4);
            *(u32*)(smem + OFF_WHI + off) = packbf(v0, v1);
            *(u32*)(smem + OFF_WLO + off) = packbf(v0 - h0, v1 - h1);
        }
    }
    __syncthreads();

    float* Zhi = (float*)(smem + OFF_ZHI);
    float* Zlo = (float*)(smem + OFF_ZLO);
    __nv_bfloat16* hsb = (__nv_bfloat16*)(smem + OFF_HSB);

    const int uglob = cb * 8 + wid;   // this warp's hidden unit
    const int b0 = lane * 2;
    float c0 = 0.f, c1 = 0.f;

    for (int t = 0; t < T; t++) {
        // prefetch xg gate values (overlaps with MMA work)
        float2 xgv[4];
#pragma unroll
        for (int g = 0; g < 4; g++)
            xgv[g] = __ldg((const float2*)(g_xg + ((size_t)t * G4H + g * H + uglob) * B + b0));

        if (t > 0) {
            const unsigned char* img = &g_hImg[(t - 1) & 1][0];
            if (wid < 4) {
                // Bhi x m-tiles {2w, 2w+1} x 4 n-tiles
                const int mt0 = wid * 2, mt1 = mt0 + 1;
                float dA[4][4], dB[4][4];
#pragma unroll
                for (int n = 0; n < 4; n++)
#pragma unroll
                    for (int p = 0; p < 4; p++) { dA[n][p] = 0.f; dB[n][p] = 0.f; }
                uint4 a0 = ldimg(img, 0, mt0, lane);
                uint4 a1 = ldimg(img, 0, mt1, lane);
                for (int kc = 0; kc < 64; kc++) {
                    uint4 n0 = a0, n1 = a1;
                    if (kc < 63) {
                        n0 = ldimg(img, kc + 1, mt0, lane);
                        n1 = ldimg(img, kc + 1, mt1, lane);
                    }
#pragma unroll
                    for (int nt = 0; nt < 4; nt++) {
                        uint2 b = *(const uint2*)(smem + OFF_WHI + ((kc * 4 + nt) * 32 + lane) * 8);
                        mma_bf16(dA[nt], a0, b.x, b.y);
                        mma_bf16(dB[nt], a1, b.x, b.y);
                    }
                    a0 = n0; a1 = n1;
                }
                int g = lane >> 2, tq = lane & 3;
#pragma unroll
                for (int nt = 0; nt < 4; nt++) {
                    int c = nt * 8 + tq * 2;
                    Zhi[(mt0 * 16 + g) * 33 + c]     = dA[nt][0];
                    Zhi[(mt0 * 16 + g) * 33 + c + 1] = dA[nt][1];
                    Zhi[(mt0 * 16 + g + 8) * 33 + c]     = dA[nt][2];
                    Zhi[(mt0 * 16 + g + 8) * 33 + c + 1] = dA[nt][3];
                    Zhi[(mt1 * 16 + g) * 33 + c]     = dB[nt][0];
                    Zhi[(mt1 * 16 + g) * 33 + c + 1] = dB[nt][1];
                    Zhi[(mt1 * 16 + g + 8) * 33 + c]     = dB[nt][2];
                    Zhi[(mt1 * 16 + g + 8) * 33 + c + 1] = dB[nt][3];
                }
            } else {
                // Blo x m-tile {w-4} (hi batches) x 4 n-tiles
                const int mt = wid - 4;
                float dA[4][4];
#pragma unroll
                for (int n = 0; n < 4; n++)
#pragma unroll
                    for (int p = 0; p < 4; p++) dA[n][p] = 0.f;
                uint4 a0 = ldimg(img, 0, mt, lane);
                for (int kc = 0; kc < 64; kc++) {
                    uint4 n0 = a0;
                    if (kc < 63) n0 = ldimg(img, kc + 1, mt, lane);
#pragma unroll
                    for (int nt = 0; nt < 4; nt++) {
                        uint2 b = *(const uint2*)(smem + OFF_WLO + ((kc * 4 + nt) * 32 + lane) * 8);
                        mma_bf16(dA[nt], a0, b.x, b.y);
                    }
                    a0 = n0;
                }
                int g = lane >> 2, tq = lane & 3;
#pragma unroll
                for (int nt = 0; nt < 4; nt++) {
                    int c = nt * 8 + tq * 2;
                    Zlo[(mt * 16 + g) * 33 + c]     = dA[nt][0];
                    Zlo[(mt * 16 + g) * 33 + c + 1] = dA[nt][1];
                    Zlo[(mt * 16 + g + 8) * 33 + c]     = dA[nt][2];
                    Zlo[(mt * 16 + g + 8) * 33 + c + 1] = dA[nt][3];
                }
            }
        }
        __syncthreads();

        // gates for cells (uglob, b0) and (uglob, b0+1)
        float z0[4], z1[4];
#pragma unroll
        for (int g = 0; g < 4; g++) {
            int j = g * 8 + wid;
            if (t > 0) {
                z0[g] = Zhi[b0 * 33 + j] + Zhi[(64 + b0) * 33 + j] + Zlo[b0 * 33 + j] + xgv[g].x;
                z1[g] = Zhi[(b0 + 1) * 33 + j] + Zhi[(64 + b0 + 1) * 33 + j] + Zlo[(b0 + 1) * 33 + j] + xgv[g].y;
            } else {
                z0[g] = xgv[g].x;
                z1[g] = xgv[g].y;
            }
        }
        float i0 = sigf(z0[0]), f0 = sigf(z0[1]), gg0 = tanhf(z0[2]), o0 = sigf(z0[3]);
        float i1 = sigf(z1[0]), f1 = sigf(z1[1]), gg1 = tanhf(z1[2]), o1 = sigf(z1[3]);
        c0 = f0 * c0 + i0 * gg0;
        c1 = f1 * c1 + i1 * gg1;
        float h0 = o0 * tanhf(c0);
        float h1 = o1 * tanhf(c1);

        // fp32 h for next layer / projection
        *(float2*)(hseq + ((size_t)t * H + uglob) * B + b0) = make_float2(h0, h1);

        // stage split h (hi rows 0-63, lo rows 64-127) as bf16
        __nv_bfloat16 hh0 = __float2bfloat16_rn(h0);
        __nv_bfloat16 hh1 = __float2bfloat16_rn(h1);
        hsb[b0 * 8 + wid] = hh0;
        hsb[(b0 + 1) * 8 + wid] = hh1;
        hsb[(64 + b0) * 8 + wid] = __float2bfloat16_rn(h0 - __bfloat162float(hh0));
        hsb[(64 + b0 + 1) * 8 + wid] = __float2bfloat16_rn(h1 - __bfloat162float(hh1));
        __syncthreads();

        // publish fragment-packed image words (this CTA owns kpairs cb*4..cb*4+3)
        {
            unsigned char* imgW = &g_hImg[t & 1][0];
            int R = tid >> 1;
            int kbase = (tid & 1) * 2;
            int ri = R & 15, mt = R >> 4;
            int wbase = ((cb & 1) << 1) | (ri >> 3);
#pragma unroll
            for (int q = 0; q < 2; q++) {
                int kpl = kbase + q;
                u32 val = *(const u32*)((const char*)hsb + (R * 8 + 2 * kpl) * 2);
                int l = ((ri & 7) << 2) | kpl;
                size_t off = ((size_t)(((cb >> 1) * 8 + mt) * 32 + l) << 4) + (size_t)wbase * 4;
                *(u32*)(imgW + off) = val;
            }
        }
        __threadfence();
        grid_barrier();
    }
}

// ---------------- kernel 4: projection ----------------
__global__ void __launch_bounds__(256)
proj_kernel(const float* __restrict__ hseq, const float* __restrict__ w_out,
            const float* __restrict__ b_out, float* __restrict__ out) {
    __shared__ float Sh[64][68];
    __shared__ float Sw[64][68];
    int t = blockIdx.x, tid = threadIdx.x;
    int fg = tid >> 4, bg = tid & 15;
    float accv[4][4];
#pragma unroll
    for (int i = 0; i < 4; i++)
#pragma unroll
        for (int j = 0; j < 4; j++) accv[i][j] = 0.f;

    for (int kc = 0; kc < H; kc += 64) {
        __syncthreads();
        {
            int i = tid >> 2, b = (tid & 3) * 16;
            const float4* src = (const float4*)(hseq + ((size_t)t * H + kc + i) * B + b);
#pragma unroll
            for (int m = 0; m < 4; m++) {
                float4 v = src[m];
                Sh[i][b + m * 4 + 0] = v.x; Sh[i][b + m * 4 + 1] = v.y;
                Sh[i][b + m * 4 + 2] = v.z; Sh[i][b + m * 4 + 3] = v.w;
            }
        }
        {
            int f = tid >> 2, kk = (tid & 3) * 16;
            const float4* src = (const float4*)(w_out + (size_t)f * H + kc + kk);
#pragma unroll
            for (int m = 0; m < 4; m++) {
                float4 v = src[m];
                Sw[kk + m * 4 + 0][f] = v.x; Sw[kk + m * 4 + 1][f] = v.y;
                Sw[kk + m * 4 + 2][f] = v.z; Sw[kk + m * 4 + 3][f] = v.w;
            }
        }
        __syncthreads();
#pragma unroll 4
        for (int k = 0; k < 64; k++) {
            float4 wv = *(const float4*)&Sw[k][fg * 4];
            float4 hv = *(const float4*)&Sh[k][bg * 4];
            float wr[4] = {wv.x, wv.y, wv.z, wv.w};
            float hr[4] = {hv.x, hv.y, hv.z, hv.w};
#pragma unroll
            for (int i = 0; i < 4; i++)
#pragma unroll
                for (int j = 0; j < 4; j++) accv[i][j] += wr[i] * hr[j];
        }
    }
    int fbase = fg * 4, bbase = bg * 4;
#pragma unroll
    for (int j = 0; j < 4; j++) {
        int b = bbase + j;
        float4 r;
        r.x = tanhf(accv[0][j] + b_out[fbase + 0]);
        r.y = tanhf(accv[1][j] + b_out[fbase + 1]);
        r.z = tanhf(accv[2][j] + b_out[fbase + 2]);
        r.w = tanhf(accv[3][j] + b_out[fbase + 3]);
        *(float4*)(out + ((size_t)b * T + t) * F + fbase) = r;
    }
}

// ---------------- launch ----------------
extern "C" void kernel_launch(void* const* d_in, const int* in_sizes, int n_in,
                              void* d_out, int out_size) {
    const float* X = (const float*)d_in[0];
    const float* w_ih[3] = {(const float*)d_in[1], (const float*)d_in[5], (const float*)d_in[9]};
    const float* w_hh[3] = {(const float*)d_in[2], (const float*)d_in[6], (const float*)d_in[10]};
    const float* b_ih[3] = {(const float*)d_in[3], (const float*)d_in[7], (const float*)d_in[11]};
    const float* b_hh[3] = {(const float*)d_in[4], (const float*)d_in[8], (const float*)d_in[12]};
    const float* w_out = (const float*)d_in[13];
    const float* b_out = (const float*)d_in[14];
    float* out = (float*)d_out;

    float *aA = nullptr, *aB = nullptr;
    cudaGetSymbolAddress((void**)&aA, g_actA);
    cudaGetSymbolAddress((void**)&aB, g_actB);

    const size_t smem_xg1 = ((size_t)F * 32 + 8 * 32 * PSTRIDE + 32) * sizeof(float);
    const size_t smem_xgH = ((size_t)H * 32 + 8 * 32 * PSTRIDE + 32) * sizeof(float);

    cudaFuncSetAttribute(xg_kernel, cudaFuncAttributeMaxDynamicSharedMemorySize, (int)smem_xgH);
    cudaFuncSetAttribute(rec_kernel, cudaFuncAttributeMaxDynamicSharedMemorySize, SMEM_REC);

    transpose_kernel<<<(T * F * B + 255) / 256, 256>>>(X, aA);

    xg_kernel<<<NCTA, NTHR, smem_xg1>>>(w_ih[0], b_ih[0], b_hh[0], aA, F);
    rec_kernel<<<NCTA, NTHR, SMEM_REC>>>(w_hh[0], aB);

    xg_kernel<<<NCTA, NTHR, smem_xgH>>>(w_ih[1], b_ih[1], b_hh[1], aB, H);
    rec_kernel<<<NCTA, NTHR, SMEM_REC>>>(w_hh[1], aA);

    xg_kernel<<<NCTA, NTHR, smem_xgH>>>(w_ih[2], b_ih[2], b_hh[2], aA, H);
    rec_kernel<<<NCTA, NTHR, SMEM_REC>>>(w_hh[2], aB);

    proj_kernel<<<T, 256>>>(aB, w_out, b_out, out);
}

// round 6
// speedup vs baseline: 2.2564x; 1.0595x over previous
#include <cuda_runtime.h>
#include <cuda_bf16.h>
#include <math.h>

#define B 64
#define T 256
#define F 64
#define H 1024
#define G4H 4096
#define NCTA 128
#define NTHR 256
#define PSTRIDE 66

typedef unsigned long long ull;
typedef unsigned int u32;

// ---------------- scratch globals ----------------
__device__ __align__(256) float g_xg[(size_t)T * G4H * B];   // [T][4096][B]
__device__ __align__(256) float g_actA[(size_t)T * H * B];   // [T][H][B]
__device__ __align__(256) float g_actB[(size_t)T * H * B];   // [T][H][B]
// fragment-packed A images: entry (kc, mt, lane) -> 16B (4 words)
__device__ __align__(256) unsigned char g_hImg[2][64 * 8 * 32 * 16];          // per-step h image
__device__ __align__(256) unsigned char g_xImg[(size_t)T * 64 * 8 * 32 * 16]; // per-t x image (64MB)
__device__ unsigned g_bar_count = 0;
__device__ unsigned g_bar_gen = 0;

// ---------------- generic helpers ----------------
__device__ __forceinline__ ull splat2(float x) {
    ull r; asm("mov.b64 %0, {%1, %1};" : "=l"(r) : "f"(x)); return r;
}
__device__ __forceinline__ void fma2(ull& d, ull a, ull b) {
    asm("fma.rn.f32x2 %0, %1, %2, %0;" : "+l"(d) : "l"(a), "l"(b));
}
__device__ __forceinline__ float sigf(float x) { return 1.f / (1.f + __expf(-x)); }

__device__ __forceinline__ void grid_barrier() {
    __syncthreads();
    if (threadIdx.x == 0) {
        unsigned gen = *(volatile unsigned*)&g_bar_gen;
        __threadfence();
        unsigned arrived = atomicAdd(&g_bar_count, 1u);
        if (arrived == gridDim.x - 1u) {
            atomicExch(&g_bar_count, 0u);
            __threadfence();
            atomicAdd(&g_bar_gen, 1u);
        } else {
            while (*(volatile unsigned*)&g_bar_gen == gen) { }
        }
    }
    __syncthreads();
}

__device__ __forceinline__ u32 packbf(float a, float b) {
    unsigned short la = __bfloat16_as_ushort(__float2bfloat16_rn(a));
    unsigned short lb = __bfloat16_as_ushort(__float2bfloat16_rn(b));
    return (u32)la | ((u32)lb << 16);
}

__device__ __forceinline__ void mma_bf16(float* d, const uint4& a, u32 b0, u32 b1) {
    asm volatile(
        "mma.sync.aligned.m16n8k16.row.col.f32.bf16.bf16.f32 "
        "{%0,%1,%2,%3},{%4,%5,%6,%7},{%8,%9},{%0,%1,%2,%3};"
        : "+f"(d[0]), "+f"(d[1]), "+f"(d[2]), "+f"(d[3])
        : "r"(a.x), "r"(a.y), "r"(a.z), "r"(a.w), "r"(b0), "r"(b1));
}

template <bool CG>
__device__ __forceinline__ uint4 ldimg(const unsigned char* img, int kc, int mt, int lane) {
    const uint4* p = (const uint4*)(img + ((size_t)((kc * 8 + mt) * 32 + lane) << 4));
    return CG ? __ldcg(p) : __ldg(p);
}

// ---------------- shared HMMA machinery ----------------
// SMEM layout (bytes), common to rec and xg_mma kernels:
#define OFF_WHI 0
#define OFF_WLO 65536
#define OFF_ZHI 131072
#define OFF_ZLO 147968
#define OFF_AUX 156416      // rec: hsb staging [128][8] bf16 (2KB); xg: bias[32] f32
#define SMEM_REC 158464

// Pack a 32-gate-column weight slice (rows (j>>3)*H + cb*8 + (j&7), K=H) into
// B-fragment layout, split hi/lo bf16.
__device__ void pack_w(const float* __restrict__ w, char* smem, int cb, int tid) {
    int nt = tid >> 6;            // 0..3
    int l  = (tid >> 1) & 31;
    int word = tid & 1;
    int j = nt * 8 + (l >> 2);    // local col 0..31
    int row = (j >> 3) * H + cb * 8 + (j & 7);
    const float* src = w + (size_t)row * H;
    for (int kc = 0; kc < 64; kc++) {
        int k0 = kc * 16 + (l & 3) * 2 + word * 8;
        float v0 = __ldg(src + k0), v1 = __ldg(src + k0 + 1);
        float h0 = __bfloat162float(__float2bfloat16_rn(v0));
        float h1 = __bfloat162float(__float2bfloat16_rn(v1));
        u32 off = (u32)(((kc * 4 + nt) * 32 + l) * 8 + word * 4);
        *(u32*)(smem + OFF_WHI + off) = packbf(v0, v1);
        *(u32*)(smem + OFF_WLO + off) = packbf(v0 - h0, v1 - h1);
    }
}

// 4-deep-pipelined K=1024 mainloop. A image is [128 rows x 1024 k] split-bf16
// (rows 0-63 hi, 64-127 lo). B = W slice (hi for warps 0-3, lo for warps 4-7).
// Writes Zhi[128][33], Zlo[64][33] in SMEM.
template <bool CG>
__device__ __forceinline__ void mma_mainloop(const unsigned char* img, char* smem,
                                             int wid, int lane) {
    float* Zhi = (float*)(smem + OFF_ZHI);
    float* Zlo = (float*)(smem + OFF_ZLO);
    if (wid < 4) {
        const int mt0 = wid * 2, mt1 = mt0 + 1;
        float dA[4][4], dB[4][4];
#pragma unroll
        for (int n = 0; n < 4; n++)
#pragma unroll
            for (int p = 0; p < 4; p++) { dA[n][p] = 0.f; dB[n][p] = 0.f; }
        uint4 s0[4], s1[4];
#pragma unroll
        for (int p = 0; p < 3; p++) {
            s0[p] = ldimg<CG>(img, p, mt0, lane);
            s1[p] = ldimg<CG>(img, p, mt1, lane);
        }
#pragma unroll 4
        for (int kc = 0; kc < 64; kc++) {
            uint4 a0 = s0[kc & 3], a1 = s1[kc & 3];
            int pf = kc + 3;
            if (pf < 64) {
                s0[pf & 3] = ldimg<CG>(img, pf, mt0, lane);
                s1[pf & 3] = ldimg<CG>(img, pf, mt1, lane);
            }
#pragma unroll
            for (int nt = 0; nt < 4; nt++) {
                uint2 b = *(const uint2*)(smem + OFF_WHI + ((kc * 4 + nt) * 32 + lane) * 8);
                mma_bf16(dA[nt], a0, b.x, b.y);
                mma_bf16(dB[nt], a1, b.x, b.y);
            }
        }
        int g = lane >> 2, tq = lane & 3;
#pragma unroll
        for (int nt = 0; nt < 4; nt++) {
            int c = nt * 8 + tq * 2;
            Zhi[(mt0 * 16 + g) * 33 + c]         = dA[nt][0];
            Zhi[(mt0 * 16 + g) * 33 + c + 1]     = dA[nt][1];
            Zhi[(mt0 * 16 + g + 8) * 33 + c]     = dA[nt][2];
            Zhi[(mt0 * 16 + g + 8) * 33 + c + 1] = dA[nt][3];
            Zhi[(mt1 * 16 + g) * 33 + c]         = dB[nt][0];
            Zhi[(mt1 * 16 + g) * 33 + c + 1]     = dB[nt][1];
            Zhi[(mt1 * 16 + g + 8) * 33 + c]     = dB[nt][2];
            Zhi[(mt1 * 16 + g + 8) * 33 + c + 1] = dB[nt][3];
        }
    } else {
        const int mt = wid - 4;
        float dA[4][4];
#pragma unroll
        for (int n = 0; n < 4; n++)
#pragma unroll
            for (int p = 0; p < 4; p++) dA[n][p] = 0.f;
        uint4 s0[4];
#pragma unroll
        for (int p = 0; p < 3; p++) s0[p] = ldimg<CG>(img, p, mt, lane);
#pragma unroll 4
        for (int kc = 0; kc < 64; kc++) {
            uint4 a0 = s0[kc & 3];
            int pf = kc + 3;
            if (pf < 64) s0[pf & 3] = ldimg<CG>(img, pf, mt, lane);
#pragma unroll
            for (int nt = 0; nt < 4; nt++) {
                uint2 b = *(const uint2*)(smem + OFF_WLO + ((kc * 4 + nt) * 32 + lane) * 8);
                mma_bf16(dA[nt], a0, b.x, b.y);
            }
        }
        int g = lane >> 2, tq = lane & 3;
#pragma unroll
        for (int nt = 0; nt < 4; nt++) {
            int c = nt * 8 + tq * 2;
            Zlo[(mt * 16 + g) * 33 + c]         = dA[nt][0];
            Zlo[(mt * 16 + g) * 33 + c + 1]     = dA[nt][1];
            Zlo[(mt * 16 + g + 8) * 33 + c]     = dA[nt][2];
            Zlo[(mt * 16 + g + 8) * 33 + c + 1] = dA[nt][3];
        }
    }
}

// ---------------- SIMT GEMM helpers (layer-1 xg, K=64) ----------------
template <bool CG>
__device__ __forceinline__ void loadpair(ulonglong2 (&dst)[2], const float* p) {
    const ulonglong2* q = (const ulonglong2*)p;
    if (CG) { dst[0] = __ldcg(q); dst[1] = __ldcg(q + 1); }
    else    { dst[0] = __ldg(q);  dst[1] = __ldg(q + 1); }
}
__device__ __forceinline__ void compute_k(const float* __restrict__ Wp,
                                          const ulonglong2 (&hb)[2], ull (&acc)[8][4]) {
    float4 w0 = *(const float4*)Wp;
    float4 w1 = *(const float4*)(Wp + 4);
    ull h4[4] = {hb[0].x, hb[0].y, hb[1].x, hb[1].y};
    float wv[8] = {w0.x, w0.y, w0.z, w0.w, w1.x, w1.y, w1.z, w1.w};
#pragma unroll
    for (int j = 0; j < 8; j++) {
        ull ws = splat2(wv[j]);
#pragma unroll
        for (int p = 0; p < 4; p++) fma2(acc[j][p], ws, h4[p]);
    }
}
template <bool USE_CG>
__device__ __forceinline__ void accum_tile(const float* __restrict__ xin,
                                           const float* __restrict__ Ws,
                                           int k0, int kcnt, int colg, int batg,
                                           ull (&acc)[8][4]) {
    const float* base = xin + (size_t)k0 * B + batg * 8;
    const float* WsK = Ws + (size_t)k0 * 32 + colg * 8;
    ulonglong2 bufA[4][2], bufB[4][2];
#pragma unroll
    for (int i = 0; i < 4; i++) loadpair<USE_CG>(bufA[i], base + (size_t)i * B);
    int nPair = kcnt >> 3;
    for (int c = 0; c < nPair; c++) {
        int kb = c * 8;
#pragma unroll
        for (int i = 0; i < 4; i++)
            loadpair<USE_CG>(bufB[i], base + (size_t)(kb + 4 + i) * B);
#pragma unroll
        for (int i = 0; i < 4; i++)
            compute_k(WsK + (size_t)(kb + i) * 32, bufA[i], acc);
        int kq = (kb + 8 < kcnt) ? kb + 8 : 0;
#pragma unroll
        for (int i = 0; i < 4; i++)
            loadpair<USE_CG>(bufA[i], base + (size_t)(kq + i) * B);
#pragma unroll
        for (int i = 0; i < 4; i++)
            compute_k(WsK + (size_t)(kb + 4 + i) * 32, bufB[i], acc);
    }
}

__device__ void load_weights(const float* __restrict__ w, int K, float* Ws, int cb) {
    for (int j = 0; j < 32; j++) {
        int cg = ((j >> 3) * H) + cb * 8 + (j & 7);
        const float* src = w + (size_t)cg * K;
        for (int k = threadIdx.x; k < K; k += NTHR)
            Ws[(size_t)k * 32 + j] = src[k];
    }
}

// ---------------- kernel 1: transpose X[b][t][f] -> A[t][f][b] ----------------
__global__ void transpose_kernel(const float* __restrict__ X, float* __restrict__ A) {
    int idx = blockIdx.x * blockDim.x + threadIdx.x;
    if (idx >= T * F * B) return;
    int b = idx & (B - 1);
    int f = (idx >> 6) & (F - 1);
    int t = idx >> 12;
    A[idx] = X[((size_t)b * T + t) * F + f];
}

// ---------------- kernel 2a: layer-1 xg (SIMT fp32, K=64) ----------------
extern "C" __global__ void __launch_bounds__(NTHR, 1)
xg_kernel(const float* __restrict__ w_ih, const float* __restrict__ b_ih,
          const float* __restrict__ b_hh, const float* __restrict__ xin, int K) {
    extern __shared__ float smemf[];
    float* Ws = smemf;
    float* part = Ws + (size_t)K * 32;
    float* bias = part + 8 * 32 * PSTRIDE;
    int cb = blockIdx.x, tid = threadIdx.x;

    load_weights(w_ih, K, Ws, cb);
    if (tid < 32) {
        int cg = ((tid >> 3) * H) + cb * 8 + (tid & 7);
        bias[tid] = b_ih[cg] + b_hh[cg];
    }
    __syncthreads();

    int w = tid >> 5, lane = tid & 31;
    int colg = lane >> 3, batg = lane & 7;
    int kpw = K / 8, k0 = w * kpw;
    int colw = tid >> 3, b0w = (tid & 7) * 8;
    int cgw = ((colw >> 3) * H) + cb * 8 + (colw & 7);

    for (int t = 0; t < T; t++) {
        ull acc[8][4];
#pragma unroll
        for (int j = 0; j < 8; j++)
#pragma unroll
            for (int p = 0; p < 4; p++) acc[j][p] = 0ull;

        const float* xp = xin + (size_t)t * K * B;
        accum_tile<false>(xp, Ws, k0, kpw, colg, batg, acc);

        float* pw = part + (size_t)w * 32 * PSTRIDE;
#pragma unroll
        for (int j = 0; j < 8; j++) {
            int col = colg * 8 + j;
#pragma unroll
            for (int p = 0; p < 4; p++)
                *(ull*)(pw + (size_t)col * PSTRIDE + batg * 8 + p * 2) = acc[j][p];
        }
        __syncthreads();

        float s[8];
        float bsum = bias[colw];
#pragma unroll
        for (int i = 0; i < 8; i++) s[i] = bsum;
#pragma unroll
        for (int ww = 0; ww < 8; ww++) {
            const float* q = part + ((size_t)ww * 32 + colw) * PSTRIDE + b0w;
#pragma unroll
            for (int i = 0; i < 8; i++) s[i] += q[i];
        }
        float* dst = g_xg + ((size_t)t * G4H + cgw) * B + b0w;
        *(float4*)dst = make_float4(s[0], s[1], s[2], s[3]);
        *(float4*)(dst + 4) = make_float4(s[4], s[5], s[6], s[7]);
        __syncthreads();
    }
}

// ---------------- kernel 2b: convert act [T][K][B] -> split-bf16 frag image ----
__global__ void __launch_bounds__(256)
cvt_kernel(const float* __restrict__ act) {
    __shared__ float xs[64][65];
    int t = blockIdx.x, tid = threadIdx.x;
    unsigned char* out = &g_xImg[(size_t)t << 18];

    for (int kb = 0; kb < H; kb += 64) {
        __syncthreads();
        {   // stage xs[kl][b] = act[t][kb+kl][b]  (coalesced)
            int kl = tid >> 2, bq = (tid & 3) * 16;
            const float4* s = (const float4*)(act + ((size_t)t * H + kb + kl) * B + bq);
#pragma unroll
            for (int m = 0; m < 4; m++) {
                float4 v = s[m];
                xs[kl][bq + m * 4 + 0] = v.x; xs[kl][bq + m * 4 + 1] = v.y;
                xs[kl][bq + m * 4 + 2] = v.z; xs[kl][bq + m * 4 + 3] = v.w;
            }
        }
        __syncthreads();
        // write fragment entries for these 4 kc
        for (int e = tid; e < 1024; e += 256) {
            int l = e & 31, mt = (e >> 5) & 7, kcL = e >> 8;
            u32 wds[4];
#pragma unroll
            for (int w = 0; w < 4; w++) {
                int r = mt * 16 + (l >> 2) + (w & 1) * 8;
                int b = r & 63;
                int kl = kcL * 16 + (l & 3) * 2 + (w >> 1) * 8;
                float f0 = xs[kl][b], f1 = xs[kl + 1][b];
                if (r < 64) {
                    wds[w] = packbf(f0, f1);
                } else {
                    float h0 = __bfloat162float(__float2bfloat16_rn(f0));
                    float h1 = __bfloat162float(__float2bfloat16_rn(f1));
                    wds[w] = packbf(f0 - h0, f1 - h1);
                }
            }
            int kc = (kb >> 4) + kcL;
            *(uint4*)(out + ((size_t)((kc * 8 + mt) * 32 + l) << 4)) =
                make_uint4(wds[0], wds[1], wds[2], wds[3]);
        }
    }
}

// ---------------- kernel 2c: xg via HMMA (layers 2-3, K=1024) ----------------
extern "C" __global__ void __launch_bounds__(NTHR, 1)
xg_mma_kernel(const float* __restrict__ w_ih, const float* __restrict__ b_ih,
              const float* __restrict__ b_hh) {
    extern __shared__ char smem[];
    const int cb = blockIdx.x, tid = threadIdx.x;
    const int wid = tid >> 5, lane = tid & 31;

    pack_w(w_ih, smem, cb, tid);
    float* bias = (float*)(smem + OFF_AUX);
    if (tid < 32) {
        int cg = ((tid >> 3) * H) + cb * 8 + (tid & 7);
        bias[tid] = b_ih[cg] + b_hh[cg];
    }
    __syncthreads();

    float* Zhi = (float*)(smem + OFF_ZHI);
    float* Zlo = (float*)(smem + OFF_ZLO);
    const int colw = tid >> 3, b0w = (tid & 7) * 8;
    const int cgw = ((colw >> 3) * H) + cb * 8 + (colw & 7);

    for (int t = 0; t < T; t++) {
        mma_mainloop<false>(&g_xImg[(size_t)t << 18], smem, wid, lane);
        __syncthreads();

        float bsum = bias[colw];
        float s[8];
#pragma unroll
        for (int i = 0; i < 8; i++) {
            int b = b0w + i;
            s[i] = Zhi[b * 33 + colw] + Zhi[(64 + b) * 33 + colw] + Zlo[b * 33 + colw] + bsum;
        }
        float* dst = g_xg + ((size_t)t * G4H + cgw) * B + b0w;
        *(float4*)dst = make_float4(s[0], s[1], s[2], s[3]);
        *(float4*)(dst + 4) = make_float4(s[4], s[5], s[6], s[7]);
        __syncthreads();
    }
}

// ---------------- kernel 3: recurrent scan — HMMA split-bf16 ----------------
extern "C" __global__ void __launch_bounds__(NTHR, 1)
rec_kernel(const float* __restrict__ w_hh, float* __restrict__ hseq) {
    extern __shared__ char smem[];
    const int cb = blockIdx.x, tid = threadIdx.x;
    const int wid = tid >> 5, lane = tid & 31;

    pack_w(w_hh, smem, cb, tid);
    __syncthreads();

    float* Zhi = (float*)(smem + OFF_ZHI);
    float* Zlo = (float*)(smem + OFF_ZLO);
    __nv_bfloat16* hsb = (__nv_bfloat16*)(smem + OFF_AUX);
    uint4* hs4 = (uint4*)(smem + OFF_AUX);
    (void)hs4;

    const int uglob = cb * 8 + wid;
    const int b0 = lane * 2;
    float c0 = 0.f, c1 = 0.f;

    for (int t = 0; t < T; t++) {
        float2 xgv[4];
#pragma unroll
        for (int g = 0; g < 4; g++)
            xgv[g] = __ldg((const float2*)(g_xg + ((size_t)t * G4H + g * H + uglob) * B + b0));

        if (t > 0)
            mma_mainloop<true>(&g_hImg[(t - 1) & 1][0], smem, wid, lane);
        __syncthreads();

        float z0[4], z1[4];
#pragma unroll
        for (int g = 0; g < 4; g++) {
            int j = g * 8 + wid;
            if (t > 0) {
                z0[g] = Zhi[b0 * 33 + j] + Zhi[(64 + b0) * 33 + j] + Zlo[b0 * 33 + j] + xgv[g].x;
                z1[g] = Zhi[(b0 + 1) * 33 + j] + Zhi[(64 + b0 + 1) * 33 + j] + Zlo[(b0 + 1) * 33 + j] + xgv[g].y;
            } else {
                z0[g] = xgv[g].x;
                z1[g] = xgv[g].y;
            }
        }
        float i0 = sigf(z0[0]), f0 = sigf(z0[1]), gg0 = tanhf(z0[2]), o0 = sigf(z0[3]);
        float i1 = sigf(z1[0]), f1 = sigf(z1[1]), gg1 = tanhf(z1[2]), o1 = sigf(z1[3]);
        c0 = f0 * c0 + i0 * gg0;
        c1 = f1 * c1 + i1 * gg1;
        float h0 = o0 * tanhf(c0);
        float h1 = o1 * tanhf(c1);

        *(float2*)(hseq + ((size_t)t * H + uglob) * B + b0) = make_float2(h0, h1);

        __nv_bfloat16 hh0 = __float2bfloat16_rn(h0);
        __nv_bfloat16 hh1 = __float2bfloat16_rn(h1);
        hsb[b0 * 8 + wid] = hh0;
        hsb[(b0 + 1) * 8 + wid] = hh1;
        hsb[(64 + b0) * 8 + wid] = __float2bfloat16_rn(h0 - __bfloat162float(hh0));
        hsb[(64 + b0 + 1) * 8 + wid] = __float2bfloat16_rn(h1 - __bfloat162float(hh1));
        __syncthreads();

        // publish fragment-packed image words (this CTA owns k = cb*8 .. cb*8+7)
        {
            unsigned char* imgW = &g_hImg[t & 1][0];
            int R = tid >> 1;
            int kbase = (tid & 1) * 2;
            int ri = R & 15, mt = R >> 4;
            int wbase = ((cb & 1) << 1) | (ri >> 3);
#pragma unroll
            for (int q = 0; q < 2; q++) {
                int kpl = kbase + q;
                u32 val = *(const u32*)((const char*)hsb + (R * 8 + 2 * kpl) * 2);
                int l = ((ri & 7) << 2) | kpl;
                size_t off = ((size_t)(((cb >> 1) * 8 + mt) * 32 + l) << 4) + (size_t)wbase * 4;
                *(u32*)(imgW + off) = val;
            }
        }
        __threadfence();
        grid_barrier();
    }
}

// ---------------- kernel 4: projection ----------------
__global__ void __launch_bounds__(256)
proj_kernel(const float* __restrict__ hseq, const float* __restrict__ w_out,
            const float* __restrict__ b_out, float* __restrict__ out) {
    __shared__ float Sh[64][68];
    __shared__ float Sw[64][68];
    int t = blockIdx.x, tid = threadIdx.x;
    int fg = tid >> 4, bg = tid & 15;
    float accv[4][4];
#pragma unroll
    for (int i = 0; i < 4; i++)
#pragma unroll
        for (int j = 0; j < 4; j++) accv[i][j] = 0.f;

    for (int kc = 0; kc < H; kc += 64) {
        __syncthreads();
        {
            int i = tid >> 2, b = (tid & 3) * 16;
            const float4* src = (const float4*)(hseq + ((size_t)t * H + kc + i) * B + b);
#pragma unroll
            for (int m = 0; m < 4; m++) {
                float4 v = src[m];
                Sh[i][b + m * 4 + 0] = v.x; Sh[i][b + m * 4 + 1] = v.y;
                Sh[i][b + m * 4 + 2] = v.z; Sh[i][b + m * 4 + 3] = v.w;
            }
        }
        {
            int f = tid >> 2, kk = (tid & 3) * 16;
            const float4* src = (const float4*)(w_out + (size_t)f * H + kc + kk);
#pragma unroll
            for (int m = 0; m < 4; m++) {
                float4 v = src[m];
                Sw[kk + m * 4 + 0][f] = v.x; Sw[kk + m * 4 + 1][f] = v.y;
                Sw[kk + m * 4 + 2][f] = v.z; Sw[kk + m * 4 + 3][f] = v.w;
            }
        }
        __syncthreads();
#pragma unroll 4
        for (int k = 0; k < 64; k++) {
            float4 wv = *(const float4*)&Sw[k][fg * 4];
            float4 hv = *(const float4*)&Sh[k][bg * 4];
            float wr[4] = {wv.x, wv.y, wv.z, wv.w};
            float hr[4] = {hv.x, hv.y, hv.z, hv.w};
#pragma unroll
            for (int i = 0; i < 4; i++)
#pragma unroll
                for (int j = 0; j < 4; j++) accv[i][j] += wr[i] * hr[j];
        }
    }
    int fbase = fg * 4, bbase = bg * 4;
#pragma unroll
    for (int j = 0; j < 4; j++) {
        int b = bbase + j;
        float4 r;
        r.x = tanhf(accv[0][j] + b_out[fbase + 0]);
        r.y = tanhf(accv[1][j] + b_out[fbase + 1]);
        r.z = tanhf(accv[2][j] + b_out[fbase + 2]);
        r.w = tanhf(accv[3][j] + b_out[fbase + 3]);
        *(float4*)(out + ((size_t)b * T + t) * F + fbase) = r;
    }
}

// ---------------- launch ----------------
extern "C" void kernel_launch(void* const* d_in, const int* in_sizes, int n_in,
                              void* d_out, int out_size) {
    const float* X = (const float*)d_in[0];
    const float* w_ih[3] = {(const float*)d_in[1], (const float*)d_in[5], (const float*)d_in[9]};
    const float* w_hh[3] = {(const float*)d_in[2], (const float*)d_in[6], (const float*)d_in[10]};
    const float* b_ih[3] = {(const float*)d_in[3], (const float*)d_in[7], (const float*)d_in[11]};
    const float* b_hh[3] = {(const float*)d_in[4], (const float*)d_in[8], (const float*)d_in[12]};
    const float* w_out = (const float*)d_in[13];
    const float* b_out = (const float*)d_in[14];
    float* out = (float*)d_out;

    float *aA = nullptr, *aB = nullptr;
    cudaGetSymbolAddress((void**)&aA, g_actA);
    cudaGetSymbolAddress((void**)&aB, g_actB);

    const size_t smem_xg1 = ((size_t)F * 32 + 8 * 32 * PSTRIDE + 32) * sizeof(float);

    cudaFuncSetAttribute(xg_kernel, cudaFuncAttributeMaxDynamicSharedMemorySize, (int)smem_xg1);
    cudaFuncSetAttribute(rec_kernel, cudaFuncAttributeMaxDynamicSharedMemorySize, SMEM_REC);
    cudaFuncSetAttribute(xg_mma_kernel, cudaFuncAttributeMaxDynamicSharedMemorySize, SMEM_REC);

    transpose_kernel<<<(T * F * B + 255) / 256, 256>>>(X, aA);

    // layer 1
    xg_kernel<<<NCTA, NTHR, smem_xg1>>>(w_ih[0], b_ih[0], b_hh[0], aA, F);
    rec_kernel<<<NCTA, NTHR, SMEM_REC>>>(w_hh[0], aB);

    // layer 2
    cvt_kernel<<<T, 256>>>(aB);
    xg_mma_kernel<<<NCTA, NTHR, SMEM_REC>>>(w_ih[1], b_ih[1], b_hh[1]);
    rec_kernel<<<NCTA, NTHR, SMEM_REC>>>(w_hh[1], aA);

    // layer 3
    cvt_kernel<<<T, 256>>>(aA);
    xg_mma_kernel<<<NCTA, NTHR, SMEM_REC>>>(w_ih[2], b_ih[2], b_hh[2]);
    rec_kernel<<<NCTA, NTHR, SMEM_REC>>>(w_hh[2], aB);

    proj_kernel<<<T, 256>>>(aB, w_out, b_out, out);
}